// round 11
// baseline (speedup 1.0000x reference)
#include <cuda_runtime.h>
#include <cuda_bf16.h>
#include <math.h>
#include <float.h>
#include <stdint.h>

// Problem constants
#define GN   32768
#define GLD  256
#define GD   512
#define KS   1024
#define KM   4096
#define NUNITS 1280   // 256 syn units + 1024 sem units (each: 128 rows x 1024 codes)

// ---------------- scratch (static __device__, no allocation) ----------------
static __device__ float g_esum_syn[KS * GD];
static __device__ float g_esum_sem[KM * GD];
static __device__ float g_counts_syn[KS];
static __device__ float g_counts_sem[KM];
static __device__ int   g_pair_syn[(size_t)KS * KS];
static __device__ int   g_pair_sem[(size_t)KM * KM];
static __device__ int   g_idx_syn[GN];
static __device__ int   g_idx_sem[GN];
static __device__ float g_cnorm_syn[KS];
static __device__ float g_cnorm_sem[KM];
static __device__ float g_clnew_syn[KS];
static __device__ float g_clnew_sem[KM];
static __device__ float g_nsum[2];
static __device__ float g_losspart[512];
static __device__ int   g_maxcn[2];   // float-as-int max of squared code norms
// bf16 copies (16B-aligned for uint4 access)
static __device__ __align__(16) __nv_bfloat16 g_zbf_syn[(size_t)GN * GD];
static __device__ __align__(16) __nv_bfloat16 g_zbf_sem[(size_t)GN * GD];
static __device__ __align__(16) __nv_bfloat16 g_cbf_syn[(size_t)KS * GD];
static __device__ __align__(16) __nv_bfloat16 g_cbf_sem[(size_t)KM * GD];
// candidates: per (unit, local row): 32 slots
static __device__ float g_cv[(size_t)NUNITS * 128 * 32];
static __device__ int   g_ck[(size_t)NUNITS * 128 * 32];

// ---------------- PTX helpers (arch-agnostic: ldmatrix + mma.sync) ----------
__device__ __forceinline__ uint32_t smem_u32(const void* p) {
    uint32_t a;
    asm("{ .reg .u64 t; cvta.to.shared.u64 t, %1; cvt.u32.u64 %0, t; }" : "=r"(a) : "l"(p));
    return a;
}
__device__ __forceinline__ void ldsm4(uint32_t& r0, uint32_t& r1, uint32_t& r2, uint32_t& r3,
                                      uint32_t addr) {
    asm volatile("ldmatrix.sync.aligned.m8n8.x4.shared.b16 {%0,%1,%2,%3}, [%4];"
                 : "=r"(r0), "=r"(r1), "=r"(r2), "=r"(r3) : "r"(addr));
}
__device__ __forceinline__ void mma_bf16(float* d, const uint32_t* a, uint32_t b0, uint32_t b1) {
    asm volatile("mma.sync.aligned.m16n8k16.row.col.f32.bf16.bf16.f32 "
                 "{%0,%1,%2,%3}, {%4,%5,%6,%7}, {%8,%9}, {%0,%1,%2,%3};"
                 : "+f"(d[0]), "+f"(d[1]), "+f"(d[2]), "+f"(d[3])
                 : "r"(a[0]), "r"(a[1]), "r"(a[2]), "r"(a[3]), "r"(b0), "r"(b1));
}

// ---------------- generic helpers ----------------
__device__ __forceinline__ float blk_reduce_256(float v) {
    __shared__ float sh[8];
    int lane = threadIdx.x & 31, w = threadIdx.x >> 5;
#pragma unroll
    for (int o = 16; o; o >>= 1) v += __shfl_down_sync(0xffffffffu, v, o);
    if (lane == 0) sh[w] = v;
    __syncthreads();
    if (w == 0) {
        v = (lane < 8) ? sh[lane] : 0.f;
#pragma unroll
        for (int o = 4; o; o >>= 1) v += __shfl_down_sync(0xffffffffu, v, o);
    }
    return v;
}

// ---------------- conversions ----------------
// 4 float4 groups per thread (MLP=4). grid = GN*GD/4096 blocks.
__global__ void cvt_z_kernel(const float* __restrict__ re, const float* __restrict__ im,
                             __nv_bfloat16* __restrict__ out) {
#pragma unroll
    for (int j = 0; j < 4; j++) {
        size_t e = (size_t)blockIdx.x * 4096 + j * 1024 + threadIdx.x * 4;
        int n = (int)(e >> 9), d = (int)(e & 511);
        const float* s = (d < GLD) ? re + (size_t)n * GLD + d
                                   : im + (size_t)n * GLD + (d - GLD);
        float4 v = *(const float4*)s;
        __nv_bfloat162 a = __floats2bfloat162_rn(v.x, v.y);
        __nv_bfloat162 b = __floats2bfloat162_rn(v.z, v.w);
        ((__nv_bfloat162*)(out + e))[0] = a;
        ((__nv_bfloat162*)(out + e))[1] = b;
    }
}

// fused codebook convert + per-row squared norms + max
__global__ void cvt_cb_norm_kernel(const float* __restrict__ cb, __nv_bfloat16* __restrict__ out,
                                   float* __restrict__ norms, int* __restrict__ mx) {
    __shared__ float sh[8];
    int t = threadIdx.x, lane = t & 31, w = t >> 5;
    size_t e = ((size_t)blockIdx.x * 256 + t) * 4;
    float4 v = *(const float4*)(cb + e);
    __nv_bfloat162 a = __floats2bfloat162_rn(v.x, v.y);
    __nv_bfloat162 b = __floats2bfloat162_rn(v.z, v.w);
    ((__nv_bfloat162*)(out + e))[0] = a;
    ((__nv_bfloat162*)(out + e))[1] = b;
    float s = v.x * v.x + v.y * v.y + v.z * v.z + v.w * v.w;
#pragma unroll
    for (int o = 16; o; o >>= 1) s += __shfl_xor_sync(0xffffffffu, s, o);
    if (lane == 0) sh[w] = s;
    __syncthreads();
    if (t == 0) {
        float n0 = sh[0] + sh[1] + sh[2] + sh[3];
        norms[blockIdx.x * 2] = n0;
        atomicMax(mx, __float_as_int(n0));
    } else if (t == 128) {
        float n1 = sh[4] + sh[5] + sh[6] + sh[7];
        norms[blockIdx.x * 2 + 1] = n1;
        atomicMax(mx, __float_as_int(n1));
    }
}

// ---------------- HMMA bf16 distance pass (4-stage LDG/STS pipeline) -------
#define SM_Z      0
#define SM_C      133120
#define SM_STAGE  18432
#define SM_TOTAL  (SM_C + 4 * SM_STAGE)   // 206848
#define SM_SV     SM_C
#define SM_SK     (SM_C + 16384)

__global__ __launch_bounds__(256, 1) void dist_hmma_kernel(
    const __nv_bfloat16* __restrict__ zbfA, const __nv_bfloat16* __restrict__ cbfA,
    const float* __restrict__ cnA,
    const __nv_bfloat16* __restrict__ zbfB, const __nv_bfloat16* __restrict__ cbfB,
    const float* __restrict__ cnB,
    float* __restrict__ cvout, int* __restrict__ ckout)
{
    extern __shared__ __align__(16) char smem[];
    char* sZ = smem + SM_Z;
    const uint32_t sbase = smem_u32(smem);

    const int tid = threadIdx.x, wid = tid >> 5, lane = tid & 31;
    const int u = blockIdx.x;

    const __nv_bfloat16 *zsrc, *csrc;
    const float* cn;
    int rowBase, kBase;
    if (u < 256) {
        zsrc = zbfA; csrc = cbfA; cn = cnA; rowBase = u * 128; kBase = 0;
    } else {
        int v = u - 256;
        zsrc = zbfB; csrc = cbfB; cn = cnB;
        rowBase = (v >> 2) * 128; kBase = (v & 3) * 1024;
    }

    // load Z tile: 128 rows x 512 bf16
#pragma unroll
    for (int i = 0; i < 32; i++) {
        int c = tid + 256 * i;       // 16B chunk id, 0..8191
        int r = c >> 6, c8 = c & 63;
        uint4 v = *(const uint4*)(zsrc + (((size_t)(rowBase + r)) << 9) + c8 * 8);
        *(uint4*)(sZ + r * 1040 + c8 * 16) = v;
    }

    const int wm = wid >> 2, wn = wid & 3;
    const uint32_t zaddr0 = sbase + SM_Z +
        (uint32_t)((wm * 64 + (lane & 15)) * 1040 + (lane >> 4) * 16);
    const uint32_t coff = (uint32_t)((wn * 32 + ((lane >> 4) << 3) + (lane & 7)) * 144 +
                                     ((lane >> 3) & 1) * 16);

    float tv[8][2]; int tk[8][2];
#pragma unroll
    for (int i = 0; i < 8; i++)
#pragma unroll
        for (int s = 0; s < 2; s++) { tv[i][s] = FLT_MAX; tk[i][s] = 0; }

    float acc[4][4][4];
#pragma unroll
    for (int mt = 0; mt < 4; mt++)
#pragma unroll
        for (int nt = 0; nt < 4; nt++)
#pragma unroll
            for (int q = 0; q < 4; q++) acc[mt][nt][q] = 0.f;

#define LDGC(pf, cc) do { \
        int _t = (cc) >> 3, _dc = (cc) & 7; \
        _Pragma("unroll") \
        for (int _j = 0; _j < 4; _j++) { \
            int _id = tid + 256 * _j; int _r = _id >> 3, _c8 = _id & 7; \
            (pf)[_j] = *(const uint4*)(csrc + (((size_t)(kBase + _t * 128 + _r)) << 9) \
                                       + _dc * 64 + _c8 * 8); \
        } \
    } while (0)
#define STSC(pf, cc) do { \
        char* _sp = smem + SM_C + ((cc) & 3) * SM_STAGE; \
        _Pragma("unroll") \
        for (int _j = 0; _j < 4; _j++) { \
            int _id = tid + 256 * _j; int _r = _id >> 3, _c8 = _id & 7; \
            *(uint4*)(_sp + _r * 144 + _c8 * 16) = (pf)[_j]; \
        } \
    } while (0)

    uint4 pfA[4], pfB[4];
    LDGC(pfA, 0); LDGC(pfB, 1);
    STSC(pfA, 0); LDGC(pfA, 2);
    STSC(pfB, 1); LDGC(pfB, 3);
    __syncthreads();

    for (int c = 0; c < 64; c++) {
        if (c + 2 < 64) {
            if (c & 1) { STSC(pfB, c + 2); if (c + 4 < 64) LDGC(pfB, c + 4); }
            else       { STSC(pfA, c + 2); if (c + 4 < 64) LDGC(pfA, c + 4); }
        }

        const int dc = c & 7;
        const uint32_t caddr0 = sbase + (uint32_t)(SM_C + (c & 3) * SM_STAGE) + coff;
#pragma unroll
        for (int ks = 0; ks < 4; ks++) {
            uint32_t b[8];
            ldsm4(b[0], b[1], b[2], b[3], caddr0 + ks * 32);
            ldsm4(b[4], b[5], b[6], b[7], caddr0 + 16 * 144 + ks * 32);
            uint32_t a[4][4];
#pragma unroll
            for (int mt = 0; mt < 4; mt++)
                ldsm4(a[mt][0], a[mt][1], a[mt][2], a[mt][3],
                      zaddr0 + (uint32_t)(mt * 16 * 1040 + (dc * 64 + ks * 16) * 2));
#pragma unroll
            for (int mt = 0; mt < 4; mt++)
#pragma unroll
                for (int nt = 0; nt < 4; nt++)
                    mma_bf16(acc[mt][nt], a[mt], b[(nt >> 1) * 4 + (nt & 1) * 2],
                             b[(nt >> 1) * 4 + (nt & 1) * 2 + 1]);
        }

        if (dc == 7) {
            const int kTile = kBase + (c >> 3) * 128;
            float cnv[8];
#pragma unroll
            for (int nt = 0; nt < 4; nt++)
#pragma unroll
                for (int cc2 = 0; cc2 < 2; cc2++)
                    cnv[nt * 2 + cc2] = __ldg(&cn[kTile + wn * 32 + nt * 8 + (lane & 3) * 2 + cc2]);
#pragma unroll
            for (int mt = 0; mt < 4; mt++)
#pragma unroll
                for (int half = 0; half < 2; half++) {
                    int i = mt * 2 + half;
#pragma unroll
                    for (int nt = 0; nt < 4; nt++)
#pragma unroll
                        for (int cc2 = 0; cc2 < 2; cc2++) {
                            int col = wn * 32 + nt * 8 + (lane & 3) * 2 + cc2;
                            float s = acc[mt][nt][half * 2 + cc2];
                            float v = fmaf(-2.f, s, cnv[nt * 2 + cc2]);
                            int k = kTile + col;
                            if (v < tv[i][0]) {
                                tv[i][1] = tv[i][0]; tk[i][1] = tk[i][0];
                                tv[i][0] = v; tk[i][0] = k;
                            } else if (v < tv[i][1]) {
                                tv[i][1] = v; tk[i][1] = k;
                            }
                        }
                }
#pragma unroll
            for (int mt = 0; mt < 4; mt++)
#pragma unroll
                for (int nt = 0; nt < 4; nt++)
#pragma unroll
                    for (int q = 0; q < 4; q++) acc[mt][nt][q] = 0.f;
        }
        __syncthreads();
    }

    float* sv = (float*)(smem + SM_SV);
    int*   sk = (int*)(smem + SM_SK);
#pragma unroll
    for (int i = 0; i < 8; i++) {
        int r = wm * 64 + (i >> 1) * 16 + (i & 1) * 8 + (lane >> 2);
        int slot0 = wn * 8 + (lane & 3) * 2;
#pragma unroll
        for (int s = 0; s < 2; s++) {
            sv[r * 32 + slot0 + s] = tv[i][s];
            sk[r * 32 + slot0 + s] = tk[i][s];
        }
    }
    __syncthreads();
#pragma unroll
    for (int j = 0; j < 16; j++) {
        int idx = tid + 256 * j;
        cvout[(size_t)u * 4096 + idx] = sv[idx];
        ckout[(size_t)u * 4096 + idx] = sk[idx];
    }
#undef LDGC
#undef STSC
}

// ---------------- exact fp32 refinement (parallel candidate preload) -------
__global__ __launch_bounds__(256) void refine_kernel(
    const float* __restrict__ zreA, const float* __restrict__ zimA,
    const float* __restrict__ cbA, const float* __restrict__ cnA,
    const float* __restrict__ zreB, const float* __restrict__ zimB,
    const float* __restrict__ cbB, const float* __restrict__ cnB,
    const float* __restrict__ cv, const int* __restrict__ ck,
    const int* __restrict__ maxcn,
    int* __restrict__ idxA, int* __restrict__ idxB)
{
    int wid = threadIdx.x >> 5, lane = threadIdx.x & 31;
    int gw = blockIdx.x * 8 + wid;
    int n = gw >> 1, cbk = gw & 1;
    const float *zre, *zim, *cb, *cn;
    int* idxo;
    int cnt;
    size_t base;
    if (cbk == 0) {
        zre = zreA; zim = zimA; cb = cbA; cn = cnA; idxo = idxA;
        cnt = 32; base = ((size_t)(n >> 7) * 128 + (n & 127)) * 32;
    } else {
        zre = zreB; zim = zimB; cb = cbB; cn = cnB; idxo = idxB;
        cnt = 128; base = ((size_t)(256 + (n >> 7) * 4) * 128 + (n & 127)) * 32;
    }

    // parallel candidate preload: candidate c at base + (c>>5)*4096 + (c&31)
    float candv[4]; int candk[4];
    const int nj = cnt >> 5;
#pragma unroll
    for (int j = 0; j < 4; j++) {
        if (j < nj) {
            size_t a = base + (size_t)j * 4096 + lane;
            candv[j] = cv[a];
            candk[j] = ck[a];
        } else { candv[j] = FLT_MAX; candk[j] = 0x7fffffff; }
    }

    float zr[16];
    float zn2 = 0.f;
#pragma unroll
    for (int j = 0; j < 16; j++) {
        int d = lane + 32 * j;
        float z = (d < GLD) ? zre[(size_t)n * GLD + d] : zim[(size_t)n * GLD + d - GLD];
        zr[j] = z;
        zn2 = fmaf(z, z, zn2);
    }
#pragma unroll
    for (int o = 16; o; o >>= 1) zn2 += __shfl_xor_sync(0xffffffffu, zn2, o);

    float vb = fminf(fminf(candv[0], candv[1]), fminf(candv[2], candv[3]));
#pragma unroll
    for (int o = 16; o; o >>= 1) vb = fminf(vb, __shfl_xor_sync(0xffffffffu, vb, o));

    // provable gate: bf16 dot error <= 2^-8 ||z|| ||c|| per side -> dist error
    // 2^-7 each -> relative window 2*2^-7 = 2^-6; small absolute slack on top.
    float maxc2 = __int_as_float(maxcn[cbk]);
    float vlim = vb + 0.015625f * sqrtf(zn2 * maxc2) + 0.125f;

    float bd = FLT_MAX; int bk = 0x7fffffff;
    for (int i = 0; i < cnt; i++) {
        float v = __shfl_sync(0xffffffffu, candv[i >> 5], i & 31);
        if (v <= vlim) {
            int k = __shfl_sync(0xffffffffu, candk[i >> 5], i & 31);
            const float* crow = cb + (size_t)k * GD;
            float s = 0.f;
#pragma unroll
            for (int j = 0; j < 16; j++) s = fmaf(zr[j], crow[lane + 32 * j], s);
#pragma unroll
            for (int o = 16; o; o >>= 1) s += __shfl_xor_sync(0xffffffffu, s, o);
            float d = fmaf(-2.f, s, cn[k]);
            if (d < bd || (d == bd && k < bk)) { bd = d; bk = k; }
        }
    }
    if (lane == 0) idxo[n] = bk;
}

// ---- fused per-row: counts/pair scatter + esum scatter + zq write + loss ----
__global__ __launch_bounds__(128) void fuse_row_kernel(
    const float* __restrict__ zre, const float* __restrict__ zim,
    const int* __restrict__ idx, const int* __restrict__ prev,
    const float* __restrict__ cb,
    float* __restrict__ counts, float* __restrict__ esum, int* __restrict__ pair, int K,
    float* __restrict__ zq, float* __restrict__ idxf, float* __restrict__ lossPart)
{
    __shared__ float sh[4];
    int n = blockIdx.x, t = threadIdx.x;
    int lane = t & 31, w = t >> 5;
    int i = idx[n];
    if (t == 0) {
        atomicAdd(&counts[i], 1.f);
        atomicAdd(&pair[(size_t)prev[n] * K + i], 1);
        idxf[n] = (float)i;
    }
    int d = t * 4;
    const float* zsrc = (d < GLD) ? zre + (size_t)n * GLD + d
                                  : zim + (size_t)n * GLD + (d - GLD);
    float4 z = *(const float4*)zsrc;
    float4 q = *(const float4*)(cb + (size_t)i * GD + d);
    *(float4*)(zq + (size_t)n * GD + d) = q;
    float dx = q.x - z.x, dy = q.y - z.y, dz = q.z - z.z, dw = q.w - z.w;
    float s = dx * dx + dy * dy + dz * dz + dw * dw;
    float* es = esum + (size_t)i * GD + d;
    atomicAdd(es + 0, z.x);
    atomicAdd(es + 1, z.y);
    atomicAdd(es + 2, z.z);
    atomicAdd(es + 3, z.w);
#pragma unroll
    for (int o = 16; o; o >>= 1) s += __shfl_down_sync(0xffffffffu, s, o);
    if (lane == 0) sh[w] = s;
    __syncthreads();
    if (t == 0) atomicAdd(&lossPart[n & 511], sh[0] + sh[1] + sh[2] + sh[3]);
}

// ---------------- cluster_size EMA + n reduction ----------------
__global__ void clnew_kernel(const float* __restrict__ cl, const float* __restrict__ counts,
                             float* __restrict__ clnew, float* __restrict__ nsum, int K)
{
    int k = blockIdx.x * 256 + threadIdx.x;
    float v = 0.f;
    if (k < K) {
        v = cl[k] * 0.99f + 0.01f * counts[k];
        clnew[k] = v;
    }
    v = blk_reduce_256(v);
    if (threadIdx.x == 0) atomicAdd(nsum, v);
}

// ---------------- codebook EMA update ----------------
__global__ void cbnew_kernel(const float* __restrict__ avg, const float* __restrict__ esum,
                             const float* __restrict__ clnew, const float* __restrict__ nsum,
                             float* __restrict__ out, int K)
{
    size_t idx = (size_t)blockIdx.x * 256 + threadIdx.x;
    int k = (int)(idx >> 9);
    float n = *nsum;
    float cs = (clnew[k] + 1e-6f) / (n + (float)K * 1e-6f) * n;
    float a = avg[idx] * 0.99f + 0.01f * esum[idx];
    out[idx] = a / cs;
}

__global__ void finalize_loss_kernel(const float* __restrict__ lacc, float* __restrict__ out) {
    __shared__ float sh[8];
    int t = threadIdx.x, lane = t & 31, w = t >> 5;
    float s = lacc[t] + lacc[t + 256];
#pragma unroll
    for (int o = 16; o; o >>= 1) s += __shfl_down_sync(0xffffffffu, s, o);
    if (lane == 0) sh[w] = s;
    __syncthreads();
    if (t == 0) {
        float v = 0.f;
#pragma unroll
        for (int j = 0; j < 8; j++) v += sh[j];
        out[0] = 1.25f * v / 16777216.f;
    }
}

// ---------------- adjacency transform (vector loads, scalar stores) --------
__device__ __forceinline__ float adj1(float a, int c) {
    if (c == 0) return a;
    float p = __powf(0.99f, (float)c);
    return fmaf(a, p, (1.f - p) * 100.f);
}
__global__ void adj_kernel(const float* __restrict__ adj, const int* __restrict__ cnt,
                           float* __restrict__ out, size_t total)
{
    size_t i = ((size_t)blockIdx.x * 256 + threadIdx.x) * 4;
    if (i >= total) return;
    int4 c = *(const int4*)(cnt + i);
    float4 a = *(const float4*)(adj + i);
    out[i + 0] = adj1(a.x, c.x);
    out[i + 1] = adj1(a.y, c.y);
    out[i + 2] = adj1(a.z, c.z);
    out[i + 3] = adj1(a.w, c.w);
}

// ---------------- launch ----------------
extern "C" void kernel_launch(void* const* d_in, const int* in_sizes, int n_in,
                              void* d_out, int out_size)
{
    const float* zre_f = (const float*)d_in[0];
    const float* zim_f = (const float*)d_in[1];
    const float* zre_s = (const float*)d_in[2];
    const float* zim_s = (const float*)d_in[3];
    const int*   prev_syn = (const int*)d_in[4];
    const int*   prev_sem = (const int*)d_in[5];
    const float* cb_syn = (const float*)d_in[6];
    const float* cb_sem = (const float*)d_in[7];
    const float* cl_syn = (const float*)d_in[8];
    const float* avg_syn = (const float*)d_in[9];
    const float* cl_sem = (const float*)d_in[10];
    const float* avg_sem = (const float*)d_in[11];
    const float* adj_syn = (const float*)d_in[12];
    const float* adj_sem = (const float*)d_in[13];

    float* out = (float*)d_out;
    const size_t OFF_ZQ_SYN = 0;
    const size_t OFF_ZQ_SEM = OFF_ZQ_SYN + (size_t)GN * GD;
    const size_t OFF_LOSS   = OFF_ZQ_SEM + (size_t)GN * GD;
    const size_t OFF_IDX_SYN = OFF_LOSS + 1;
    const size_t OFF_IDX_SEM = OFF_IDX_SYN + GN;
    const size_t OFF_CB_SYN  = OFF_IDX_SEM + GN;
    const size_t OFF_CB_SEM  = OFF_CB_SYN + (size_t)KS * GD;
    const size_t OFF_ADJ_SYN = OFF_CB_SEM + (size_t)KM * GD;
    const size_t OFF_ADJ_SEM = OFF_ADJ_SYN + (size_t)KS * KS;

    void *p_esum_syn, *p_esum_sem, *p_cnt_syn, *p_cnt_sem, *p_pair_syn, *p_pair_sem;
    void *p_idx_syn, *p_idx_sem, *p_cn_syn, *p_cn_sem, *p_cl_syn, *p_cl_sem, *p_nsum, *p_loss;
    void *p_maxcn, *p_zbf_syn, *p_zbf_sem, *p_cbf_syn, *p_cbf_sem, *p_cv, *p_ck;
    cudaGetSymbolAddress(&p_esum_syn, g_esum_syn);
    cudaGetSymbolAddress(&p_esum_sem, g_esum_sem);
    cudaGetSymbolAddress(&p_cnt_syn, g_counts_syn);
    cudaGetSymbolAddress(&p_cnt_sem, g_counts_sem);
    cudaGetSymbolAddress(&p_pair_syn, g_pair_syn);
    cudaGetSymbolAddress(&p_pair_sem, g_pair_sem);
    cudaGetSymbolAddress(&p_idx_syn, g_idx_syn);
    cudaGetSymbolAddress(&p_idx_sem, g_idx_sem);
    cudaGetSymbolAddress(&p_cn_syn, g_cnorm_syn);
    cudaGetSymbolAddress(&p_cn_sem, g_cnorm_sem);
    cudaGetSymbolAddress(&p_cl_syn, g_clnew_syn);
    cudaGetSymbolAddress(&p_cl_sem, g_clnew_sem);
    cudaGetSymbolAddress(&p_nsum, g_nsum);
    cudaGetSymbolAddress(&p_loss, g_losspart);
    cudaGetSymbolAddress(&p_maxcn, g_maxcn);
    cudaGetSymbolAddress(&p_zbf_syn, g_zbf_syn);
    cudaGetSymbolAddress(&p_zbf_sem, g_zbf_sem);
    cudaGetSymbolAddress(&p_cbf_syn, g_cbf_syn);
    cudaGetSymbolAddress(&p_cbf_sem, g_cbf_sem);
    cudaGetSymbolAddress(&p_cv, g_cv);
    cudaGetSymbolAddress(&p_ck, g_ck);

    cudaFuncSetAttribute(dist_hmma_kernel,
                         cudaFuncAttributeMaxDynamicSharedMemorySize, SM_TOTAL);

    // 1) zero scratch
    cudaMemsetAsync(p_esum_syn, 0, (size_t)KS * GD * sizeof(float));
    cudaMemsetAsync(p_esum_sem, 0, (size_t)KM * GD * sizeof(float));
    cudaMemsetAsync(p_cnt_syn, 0, KS * sizeof(float));
    cudaMemsetAsync(p_cnt_sem, 0, KM * sizeof(float));
    cudaMemsetAsync(p_pair_syn, 0, (size_t)KS * KS * sizeof(int));
    cudaMemsetAsync(p_pair_sem, 0, (size_t)KM * KM * sizeof(int));
    cudaMemsetAsync(p_nsum, 0, 2 * sizeof(float));
    cudaMemsetAsync(p_loss, 0, 512 * sizeof(float));
    cudaMemsetAsync(p_maxcn, 0, 2 * sizeof(int));

    // 2) conversions (+ fused codebook norms)
    cvt_z_kernel<<<(GN * GD) / 4096, 256>>>(zre_f, zim_f, (__nv_bfloat16*)p_zbf_syn);
    cvt_z_kernel<<<(GN * GD) / 4096, 256>>>(zre_s, zim_s, (__nv_bfloat16*)p_zbf_sem);
    cvt_cb_norm_kernel<<<KS / 2, 256>>>(cb_syn, (__nv_bfloat16*)p_cbf_syn,
                                        (float*)p_cn_syn, (int*)p_maxcn);
    cvt_cb_norm_kernel<<<KM / 2, 256>>>(cb_sem, (__nv_bfloat16*)p_cbf_sem,
                                        (float*)p_cn_sem, ((int*)p_maxcn) + 1);

    // 3) HMMA approximate distance pass
    dist_hmma_kernel<<<NUNITS, 256, SM_TOTAL>>>(
        (const __nv_bfloat16*)p_zbf_syn, (const __nv_bfloat16*)p_cbf_syn, (const float*)p_cn_syn,
        (const __nv_bfloat16*)p_zbf_sem, (const __nv_bfloat16*)p_cbf_sem, (const float*)p_cn_sem,
        (float*)p_cv, (int*)p_ck);

    // 4) exact fp32 refinement -> final indices
    refine_kernel<<<(2 * GN) / 8, 256>>>(
        zre_f, zim_f, cb_syn, (const float*)p_cn_syn,
        zre_s, zim_s, cb_sem, (const float*)p_cn_sem,
        (const float*)p_cv, (const int*)p_ck, (const int*)p_maxcn,
        (int*)p_idx_syn, (int*)p_idx_sem);

    // 5) fused per-row scatter + zq + loss
    fuse_row_kernel<<<GN, 128>>>(zre_f, zim_f, (const int*)p_idx_syn, prev_syn, cb_syn,
                                 (float*)p_cnt_syn, (float*)p_esum_syn, (int*)p_pair_syn, KS,
                                 out + OFF_ZQ_SYN, out + OFF_IDX_SYN, (float*)p_loss);
    fuse_row_kernel<<<GN, 128>>>(zre_s, zim_s, (const int*)p_idx_sem, prev_sem, cb_sem,
                                 (float*)p_cnt_sem, (float*)p_esum_sem, (int*)p_pair_sem, KM,
                                 out + OFF_ZQ_SEM, out + OFF_IDX_SEM, (float*)p_loss);

    // 6) cluster size EMA + n
    clnew_kernel<<<KS / 256, 256>>>(cl_syn, (const float*)p_cnt_syn,
                                    (float*)p_cl_syn, (float*)p_nsum, KS);
    clnew_kernel<<<KM / 256, 256>>>(cl_sem, (const float*)p_cnt_sem,
                                    (float*)p_cl_sem, ((float*)p_nsum) + 1, KM);

    // 7) codebook EMA update
    cbnew_kernel<<<(KS * GD) / 256, 256>>>(avg_syn, (const float*)p_esum_syn,
                                           (const float*)p_cl_syn, (const float*)p_nsum,
                                           out + OFF_CB_SYN, KS);
    cbnew_kernel<<<(KM * GD) / 256, 256>>>(avg_sem, (const float*)p_esum_sem,
                                           (const float*)p_cl_sem, ((const float*)p_nsum) + 1,
                                           out + OFF_CB_SEM, KM);

    // 8) loss finalize
    finalize_loss_kernel<<<1, 256>>>((const float*)p_loss, out + OFF_LOSS);

    // 9) adjacency transform
    {
        size_t tot = (size_t)KS * KS;
        adj_kernel<<<(unsigned)(tot / 1024), 256>>>(adj_syn, (const int*)p_pair_syn,
                                                    out + OFF_ADJ_SYN, tot);
    }
    {
        size_t tot = (size_t)KM * KM;
        adj_kernel<<<(unsigned)(tot / 1024), 256>>>(adj_sem, (const int*)p_pair_sem,
                                                    out + OFF_ADJ_SEM, tot);
    }
    (void)in_sizes; (void)n_in; (void)out_size;
}

// round 12
// speedup vs baseline: 1.0681x; 1.0681x over previous
#include <cuda_runtime.h>
#include <cuda_bf16.h>
#include <math.h>
#include <float.h>
#include <stdint.h>

// Problem constants
#define GN   32768
#define GLD  256
#define GD   512
#define KS   1024
#define KM   4096
// 64-row units: 512 syn + 2048 sem (512 row-tiles x 4 k-chunks)
#define NUNITS2 2560

// ---------------- scratch (static __device__, no allocation) ----------------
static __device__ float g_esum_syn[KS * GD];
static __device__ float g_esum_sem[KM * GD];
static __device__ float g_counts_syn[KS];
static __device__ float g_counts_sem[KM];
static __device__ int   g_pair_syn[(size_t)KS * KS];
static __device__ int   g_pair_sem[(size_t)KM * KM];
static __device__ int   g_idx_syn[GN];
static __device__ int   g_idx_sem[GN];
static __device__ float g_cnorm_syn[KS];
static __device__ float g_cnorm_sem[KM];
static __device__ float g_clnew_syn[KS];
static __device__ float g_clnew_sem[KM];
static __device__ float g_nsum[2];
static __device__ float g_losspart[512];
static __device__ int   g_maxcn[2];   // float-as-int max of squared code norms
// bf16 copies (16B-aligned for uint4 access)
static __device__ __align__(16) __nv_bfloat16 g_zbf_syn[(size_t)GN * GD];
static __device__ __align__(16) __nv_bfloat16 g_zbf_sem[(size_t)GN * GD];
static __device__ __align__(16) __nv_bfloat16 g_cbf_syn[(size_t)KS * GD];
static __device__ __align__(16) __nv_bfloat16 g_cbf_sem[(size_t)KM * GD];
// candidates: per (unit): 64 rows x 32 slots = 2048 entries
static __device__ float g_cv[(size_t)NUNITS2 * 2048];
static __device__ int   g_ck[(size_t)NUNITS2 * 2048];

// ---------------- PTX helpers (arch-agnostic: ldmatrix + mma.sync) ----------
__device__ __forceinline__ uint32_t smem_u32(const void* p) {
    uint32_t a;
    asm("{ .reg .u64 t; cvta.to.shared.u64 t, %1; cvt.u32.u64 %0, t; }" : "=r"(a) : "l"(p));
    return a;
}
__device__ __forceinline__ void ldsm4(uint32_t& r0, uint32_t& r1, uint32_t& r2, uint32_t& r3,
                                      uint32_t addr) {
    asm volatile("ldmatrix.sync.aligned.m8n8.x4.shared.b16 {%0,%1,%2,%3}, [%4];"
                 : "=r"(r0), "=r"(r1), "=r"(r2), "=r"(r3) : "r"(addr));
}
__device__ __forceinline__ void mma_bf16(float* d, const uint32_t* a, uint32_t b0, uint32_t b1) {
    asm volatile("mma.sync.aligned.m16n8k16.row.col.f32.bf16.bf16.f32 "
                 "{%0,%1,%2,%3}, {%4,%5,%6,%7}, {%8,%9}, {%0,%1,%2,%3};"
                 : "+f"(d[0]), "+f"(d[1]), "+f"(d[2]), "+f"(d[3])
                 : "r"(a[0]), "r"(a[1]), "r"(a[2]), "r"(a[3]), "r"(b0), "r"(b1));
}

// ---------------- generic helpers ----------------
__device__ __forceinline__ float blk_reduce_256(float v) {
    __shared__ float sh[8];
    int lane = threadIdx.x & 31, w = threadIdx.x >> 5;
#pragma unroll
    for (int o = 16; o; o >>= 1) v += __shfl_down_sync(0xffffffffu, v, o);
    if (lane == 0) sh[w] = v;
    __syncthreads();
    if (w == 0) {
        v = (lane < 8) ? sh[lane] : 0.f;
#pragma unroll
        for (int o = 4; o; o >>= 1) v += __shfl_down_sync(0xffffffffu, v, o);
    }
    return v;
}

// ---------------- conversions ----------------
__global__ void cvt_z_kernel(const float* __restrict__ re, const float* __restrict__ im,
                             __nv_bfloat16* __restrict__ out) {
#pragma unroll
    for (int j = 0; j < 4; j++) {
        size_t e = (size_t)blockIdx.x * 4096 + j * 1024 + threadIdx.x * 4;
        int n = (int)(e >> 9), d = (int)(e & 511);
        const float* s = (d < GLD) ? re + (size_t)n * GLD + d
                                   : im + (size_t)n * GLD + (d - GLD);
        float4 v = *(const float4*)s;
        __nv_bfloat162 a = __floats2bfloat162_rn(v.x, v.y);
        __nv_bfloat162 b = __floats2bfloat162_rn(v.z, v.w);
        ((__nv_bfloat162*)(out + e))[0] = a;
        ((__nv_bfloat162*)(out + e))[1] = b;
    }
}

// fused codebook convert + per-row squared norms + max
__global__ void cvt_cb_norm_kernel(const float* __restrict__ cb, __nv_bfloat16* __restrict__ out,
                                   float* __restrict__ norms, int* __restrict__ mx) {
    __shared__ float sh[8];
    int t = threadIdx.x, lane = t & 31, w = t >> 5;
    size_t e = ((size_t)blockIdx.x * 256 + t) * 4;
    float4 v = *(const float4*)(cb + e);
    __nv_bfloat162 a = __floats2bfloat162_rn(v.x, v.y);
    __nv_bfloat162 b = __floats2bfloat162_rn(v.z, v.w);
    ((__nv_bfloat162*)(out + e))[0] = a;
    ((__nv_bfloat162*)(out + e))[1] = b;
    float s = v.x * v.x + v.y * v.y + v.z * v.z + v.w * v.w;
#pragma unroll
    for (int o = 16; o; o >>= 1) s += __shfl_xor_sync(0xffffffffu, s, o);
    if (lane == 0) sh[w] = s;
    __syncthreads();
    if (t == 0) {
        float n0 = sh[0] + sh[1] + sh[2] + sh[3];
        norms[blockIdx.x * 2] = n0;
        atomicMax(mx, __float_as_int(n0));
    } else if (t == 128) {
        float n1 = sh[4] + sh[5] + sh[6] + sh[7];
        norms[blockIdx.x * 2 + 1] = n1;
        atomicMax(mx, __float_as_int(n1));
    }
}

// ---------------- HMMA bf16 distance pass (64-row units, occupancy 2) ------
// Per unit (CTA, 256 thr = 8 warps in 2m x 4n): 64 rows x 1024 codes, D=512.
// Z resident in SMEM (64 x 512 bf16, row stride 1040B = 16B skew).
// cn table (1024 floats) resident in SMEM.
// Codebook streamed in 128 x 64 chunks (row stride 144B), single stage buffer,
// register prefetch (round-4 proven scheme). 87KB SMEM -> 2 CTAs per SM.
#define SM2_Z      0
#define SM2_C      66560
#define SM2_CN     (66560 + 18432)            // 84992
#define SM2_TOTAL  (SM2_CN + 4096)            // 89088
#define SM2_SV     SM2_Z
#define SM2_SK     (SM2_Z + 8192)

__global__ __launch_bounds__(256, 2) void dist_hmma_kernel(
    const __nv_bfloat16* __restrict__ zbfA, const __nv_bfloat16* __restrict__ cbfA,
    const float* __restrict__ cnA,
    const __nv_bfloat16* __restrict__ zbfB, const __nv_bfloat16* __restrict__ cbfB,
    const float* __restrict__ cnB,
    float* __restrict__ cvout, int* __restrict__ ckout)
{
    extern __shared__ __align__(16) char smem[];
    char* sZ = smem + SM2_Z;
    char* sC = smem + SM2_C;
    float* sCN = (float*)(smem + SM2_CN);
    const uint32_t sbase = smem_u32(smem);

    const int tid = threadIdx.x, wid = tid >> 5, lane = tid & 31;
    const int u = blockIdx.x;

    const __nv_bfloat16 *zsrc, *csrc;
    const float* cn;
    int rowBase, kBase;
    if (u < 512) {
        zsrc = zbfA; csrc = cbfA; cn = cnA; rowBase = u * 64; kBase = 0;
    } else {
        int v = u - 512;
        zsrc = zbfB; csrc = cbfB; cn = cnB;
        rowBase = (v >> 2) * 64; kBase = (v & 3) * 1024;
    }

    // load Z tile: 64 rows x 512 bf16
#pragma unroll
    for (int i = 0; i < 16; i++) {
        int c = tid + 256 * i;       // 16B chunk id, 0..4095
        int r = c >> 6, c8 = c & 63;
        uint4 v = *(const uint4*)(zsrc + (((size_t)(rowBase + r)) << 9) + c8 * 8);
        *(uint4*)(sZ + r * 1040 + c8 * 16) = v;
    }
    // load cn table: 1024 floats
#pragma unroll
    for (int j = 0; j < 4; j++) {
        int idx = tid + 256 * j;
        sCN[idx] = cn[kBase + idx];
    }

    const int wm = wid >> 2, wn = wid & 3;     // warp rows: wm*32..+31; cols: wn*32..+31
    const uint32_t zaddr0 = sbase + SM2_Z +
        (uint32_t)((wm * 32 + (lane & 15)) * 1040 + (lane >> 4) * 16);
    const uint32_t caddr0 = sbase + SM2_C +
        (uint32_t)((wn * 32 + ((lane >> 4) << 3) + (lane & 7)) * 144 + ((lane >> 3) & 1) * 16);

    float tv[4][2]; int tk[4][2];
#pragma unroll
    for (int i = 0; i < 4; i++)
#pragma unroll
        for (int s = 0; s < 2; s++) { tv[i][s] = FLT_MAX; tk[i][s] = 0; }

    float acc[2][4][4];
#pragma unroll
    for (int mt = 0; mt < 2; mt++)
#pragma unroll
        for (int nt = 0; nt < 4; nt++)
#pragma unroll
            for (int q = 0; q < 4; q++) acc[mt][nt][q] = 0.f;

    // load chunk cc of the codebook stream into the prefetch register set
#define LDGC(pf, cc) do { \
        int _t = (cc) >> 3, _dc = (cc) & 7; \
        _Pragma("unroll") \
        for (int _j = 0; _j < 4; _j++) { \
            int _id = tid + 256 * _j; int _r = _id >> 3, _c8 = _id & 7; \
            (pf)[_j] = *(const uint4*)(csrc + (((size_t)(kBase + _t * 128 + _r)) << 9) \
                                       + _dc * 64 + _c8 * 8); \
        } \
    } while (0)

    uint4 pf[4];
    LDGC(pf, 0);

    for (int c = 0; c < 64; c++) {
        __syncthreads();   // previous chunk's compute done -> safe to overwrite stage
#pragma unroll
        for (int j = 0; j < 4; j++) {
            int id = tid + 256 * j, r = id >> 3, c8 = id & 7;
            *(uint4*)(sC + r * 144 + c8 * 16) = pf[j];
        }
        if (c + 1 < 64) LDGC(pf, c + 1);
        __syncthreads();   // stage visible to all

        const int dc = c & 7;
#pragma unroll
        for (int ks = 0; ks < 4; ks++) {
            uint32_t b[8];
            ldsm4(b[0], b[1], b[2], b[3], caddr0 + ks * 32);
            ldsm4(b[4], b[5], b[6], b[7], caddr0 + 16 * 144 + ks * 32);
            uint32_t a[2][4];
#pragma unroll
            for (int mt = 0; mt < 2; mt++)
                ldsm4(a[mt][0], a[mt][1], a[mt][2], a[mt][3],
                      zaddr0 + (uint32_t)(mt * 16 * 1040 + (dc * 64 + ks * 16) * 2));
#pragma unroll
            for (int mt = 0; mt < 2; mt++)
#pragma unroll
                for (int nt = 0; nt < 4; nt++)
                    mma_bf16(acc[mt][nt], a[mt], b[(nt >> 1) * 4 + (nt & 1) * 2],
                             b[(nt >> 1) * 4 + (nt & 1) * 2 + 1]);
        }

        if (dc == 7) {
            // epilogue: fold tile into per-thread top-2 per row
            const int tbase = (c >> 3) * 128;
#pragma unroll
            for (int mt = 0; mt < 2; mt++)
#pragma unroll
                for (int half = 0; half < 2; half++) {
                    int i = mt * 2 + half;
#pragma unroll
                    for (int nt = 0; nt < 4; nt++)
#pragma unroll
                        for (int cc2 = 0; cc2 < 2; cc2++) {
                            int col = wn * 32 + nt * 8 + (lane & 3) * 2 + cc2;
                            float s = acc[mt][nt][half * 2 + cc2];
                            float v = fmaf(-2.f, s, sCN[tbase + col]);
                            int k = kBase + tbase + col;
                            if (v < tv[i][0]) {
                                tv[i][1] = tv[i][0]; tk[i][1] = tk[i][0];
                                tv[i][0] = v; tk[i][0] = k;
                            } else if (v < tv[i][1]) {
                                tv[i][1] = v; tk[i][1] = k;
                            }
                        }
                }
#pragma unroll
            for (int mt = 0; mt < 2; mt++)
#pragma unroll
                for (int nt = 0; nt < 4; nt++)
#pragma unroll
                    for (int q = 0; q < 4; q++) acc[mt][nt][q] = 0.f;
        }
    }

    // stage candidates in SMEM (reuse Z area), then coalesced store
    __syncthreads();
    float* sv = (float*)(smem + SM2_SV);
    int*   sk = (int*)(smem + SM2_SK);
#pragma unroll
    for (int i = 0; i < 4; i++) {
        int r = wm * 32 + (i >> 1) * 16 + (i & 1) * 8 + (lane >> 2);
        int slot0 = wn * 8 + (lane & 3) * 2;
#pragma unroll
        for (int s = 0; s < 2; s++) {
            sv[r * 32 + slot0 + s] = tv[i][s];
            sk[r * 32 + slot0 + s] = tk[i][s];
        }
    }
    __syncthreads();
#pragma unroll
    for (int j = 0; j < 8; j++) {
        int idx = tid + 256 * j;
        cvout[(size_t)u * 2048 + idx] = sv[idx];
        ckout[(size_t)u * 2048 + idx] = sk[idx];
    }
#undef LDGC
}

// ---------------- exact fp32 refinement (parallel candidate preload) -------
// Candidate layout: unit u, row r, slot s at u*2048 + r*32 + s.
// syn row n: unit n>>6 (32 candidates). sem row n: units 512+(n>>6)*4+j, j=0..3.
__global__ __launch_bounds__(256) void refine_kernel(
    const float* __restrict__ zreA, const float* __restrict__ zimA,
    const float* __restrict__ cbA, const float* __restrict__ cnA,
    const float* __restrict__ zreB, const float* __restrict__ zimB,
    const float* __restrict__ cbB, const float* __restrict__ cnB,
    const float* __restrict__ cv, const int* __restrict__ ck,
    const int* __restrict__ maxcn,
    int* __restrict__ idxA, int* __restrict__ idxB)
{
    int wid = threadIdx.x >> 5, lane = threadIdx.x & 31;
    int gw = blockIdx.x * 8 + wid;
    int n = gw >> 1, cbk = gw & 1;
    const float *zre, *zim, *cb, *cn;
    int* idxo;
    int cnt;
    size_t base;
    if (cbk == 0) {
        zre = zreA; zim = zimA; cb = cbA; cn = cnA; idxo = idxA;
        cnt = 32;
        base = (size_t)(n >> 6) * 2048 + (size_t)(n & 63) * 32;
    } else {
        zre = zreB; zim = zimB; cb = cbB; cn = cnB; idxo = idxB;
        cnt = 128;
        base = (size_t)(512 + (n >> 6) * 4) * 2048 + (size_t)(n & 63) * 32;
    }

    // parallel candidate preload: candidate c = j*32 + s at base + j*2048 + s
    float candv[4]; int candk[4];
    const int nj = cnt >> 5;
#pragma unroll
    for (int j = 0; j < 4; j++) {
        if (j < nj) {
            size_t a = base + (size_t)j * 2048 + lane;
            candv[j] = cv[a];
            candk[j] = ck[a];
        } else { candv[j] = FLT_MAX; candk[j] = 0x7fffffff; }
    }

    float zr[16];
    float zn2 = 0.f;
#pragma unroll
    for (int j = 0; j < 16; j++) {
        int d = lane + 32 * j;
        float z = (d < GLD) ? zre[(size_t)n * GLD + d] : zim[(size_t)n * GLD + d - GLD];
        zr[j] = z;
        zn2 = fmaf(z, z, zn2);
    }
#pragma unroll
    for (int o = 16; o; o >>= 1) zn2 += __shfl_xor_sync(0xffffffffu, zn2, o);

    float vb = fminf(fminf(candv[0], candv[1]), fminf(candv[2], candv[3]));
#pragma unroll
    for (int o = 16; o; o >>= 1) vb = fminf(vb, __shfl_xor_sync(0xffffffffu, vb, o));

    float maxc2 = __int_as_float(maxcn[cbk]);
    float vlim = vb + 0.03125f * sqrtf(zn2 * maxc2) + 0.125f;

    float bd = FLT_MAX; int bk = 0x7fffffff;
    for (int i = 0; i < cnt; i++) {
        float v = __shfl_sync(0xffffffffu, candv[i >> 5], i & 31);
        if (v <= vlim) {
            int k = __shfl_sync(0xffffffffu, candk[i >> 5], i & 31);
            const float* crow = cb + (size_t)k * GD;
            float s = 0.f;
#pragma unroll
            for (int j = 0; j < 16; j++) s = fmaf(zr[j], crow[lane + 32 * j], s);
#pragma unroll
            for (int o = 16; o; o >>= 1) s += __shfl_xor_sync(0xffffffffu, s, o);
            float d = fmaf(-2.f, s, cn[k]);
            if (d < bd || (d == bd && k < bk)) { bd = d; bk = k; }
        }
    }
    if (lane == 0) idxo[n] = bk;
}

// ---- fused per-row: counts/pair scatter + esum scatter + zq write + loss ----
__global__ __launch_bounds__(128) void fuse_row_kernel(
    const float* __restrict__ zre, const float* __restrict__ zim,
    const int* __restrict__ idx, const int* __restrict__ prev,
    const float* __restrict__ cb,
    float* __restrict__ counts, float* __restrict__ esum, int* __restrict__ pair, int K,
    float* __restrict__ zq, float* __restrict__ idxf, float* __restrict__ lossPart)
{
    __shared__ float sh[4];
    int n = blockIdx.x, t = threadIdx.x;
    int lane = t & 31, w = t >> 5;
    int i = idx[n];
    if (t == 0) {
        atomicAdd(&counts[i], 1.f);
        atomicAdd(&pair[(size_t)prev[n] * K + i], 1);
        idxf[n] = (float)i;
    }
    int d = t * 4;
    const float* zsrc = (d < GLD) ? zre + (size_t)n * GLD + d
                                  : zim + (size_t)n * GLD + (d - GLD);
    float4 z = *(const float4*)zsrc;
    float4 q = *(const float4*)(cb + (size_t)i * GD + d);
    *(float4*)(zq + (size_t)n * GD + d) = q;
    float dx = q.x - z.x, dy = q.y - z.y, dz = q.z - z.z, dw = q.w - z.w;
    float s = dx * dx + dy * dy + dz * dz + dw * dw;
    float* es = esum + (size_t)i * GD + d;
    atomicAdd(es + 0, z.x);
    atomicAdd(es + 1, z.y);
    atomicAdd(es + 2, z.z);
    atomicAdd(es + 3, z.w);
#pragma unroll
    for (int o = 16; o; o >>= 1) s += __shfl_down_sync(0xffffffffu, s, o);
    if (lane == 0) sh[w] = s;
    __syncthreads();
    if (t == 0) atomicAdd(&lossPart[n & 511], sh[0] + sh[1] + sh[2] + sh[3]);
}

// ---------------- cluster_size EMA + n reduction ----------------
__global__ void clnew_kernel(const float* __restrict__ cl, const float* __restrict__ counts,
                             float* __restrict__ clnew, float* __restrict__ nsum, int K)
{
    int k = blockIdx.x * 256 + threadIdx.x;
    float v = 0.f;
    if (k < K) {
        v = cl[k] * 0.99f + 0.01f * counts[k];
        clnew[k] = v;
    }
    v = blk_reduce_256(v);
    if (threadIdx.x == 0) atomicAdd(nsum, v);
}

// ---------------- codebook EMA update ----------------
__global__ void cbnew_kernel(const float* __restrict__ avg, const float* __restrict__ esum,
                             const float* __restrict__ clnew, const float* __restrict__ nsum,
                             float* __restrict__ out, int K)
{
    size_t idx = (size_t)blockIdx.x * 256 + threadIdx.x;
    int k = (int)(idx >> 9);
    float n = *nsum;
    float cs = (clnew[k] + 1e-6f) / (n + (float)K * 1e-6f) * n;
    float a = avg[idx] * 0.99f + 0.01f * esum[idx];
    out[idx] = a / cs;
}

__global__ void finalize_loss_kernel(const float* __restrict__ lacc, float* __restrict__ out) {
    __shared__ float sh[8];
    int t = threadIdx.x, lane = t & 31, w = t >> 5;
    float s = lacc[t] + lacc[t + 256];
#pragma unroll
    for (int o = 16; o; o >>= 1) s += __shfl_down_sync(0xffffffffu, s, o);
    if (lane == 0) sh[w] = s;
    __syncthreads();
    if (t == 0) {
        float v = 0.f;
#pragma unroll
        for (int j = 0; j < 8; j++) v += sh[j];
        out[0] = 1.25f * v / 16777216.f;
    }
}

// ---------------- adjacency transform (vector loads, scalar stores) --------
__device__ __forceinline__ float adj1(float a, int c) {
    if (c == 0) return a;
    float p = __powf(0.99f, (float)c);
    return fmaf(a, p, (1.f - p) * 100.f);
}
__global__ void adj_kernel(const float* __restrict__ adj, const int* __restrict__ cnt,
                           float* __restrict__ out, size_t total)
{
    size_t i = ((size_t)blockIdx.x * 256 + threadIdx.x) * 4;
    if (i >= total) return;
    int4 c = *(const int4*)(cnt + i);
    float4 a = *(const float4*)(adj + i);
    out[i + 0] = adj1(a.x, c.x);
    out[i + 1] = adj1(a.y, c.y);
    out[i + 2] = adj1(a.z, c.z);
    out[i + 3] = adj1(a.w, c.w);
}

// ---------------- launch ----------------
extern "C" void kernel_launch(void* const* d_in, const int* in_sizes, int n_in,
                              void* d_out, int out_size)
{
    const float* zre_f = (const float*)d_in[0];
    const float* zim_f = (const float*)d_in[1];
    const float* zre_s = (const float*)d_in[2];
    const float* zim_s = (const float*)d_in[3];
    const int*   prev_syn = (const int*)d_in[4];
    const int*   prev_sem = (const int*)d_in[5];
    const float* cb_syn = (const float*)d_in[6];
    const float* cb_sem = (const float*)d_in[7];
    const float* cl_syn = (const float*)d_in[8];
    const float* avg_syn = (const float*)d_in[9];
    const float* cl_sem = (const float*)d_in[10];
    const float* avg_sem = (const float*)d_in[11];
    const float* adj_syn = (const float*)d_in[12];
    const float* adj_sem = (const float*)d_in[13];

    float* out = (float*)d_out;
    const size_t OFF_ZQ_SYN = 0;
    const size_t OFF_ZQ_SEM = OFF_ZQ_SYN + (size_t)GN * GD;
    const size_t OFF_LOSS   = OFF_ZQ_SEM + (size_t)GN * GD;
    const size_t OFF_IDX_SYN = OFF_LOSS + 1;
    const size_t OFF_IDX_SEM = OFF_IDX_SYN + GN;
    const size_t OFF_CB_SYN  = OFF_IDX_SEM + GN;
    const size_t OFF_CB_SEM  = OFF_CB_SYN + (size_t)KS * GD;
    const size_t OFF_ADJ_SYN = OFF_CB_SEM + (size_t)KM * GD;
    const size_t OFF_ADJ_SEM = OFF_ADJ_SYN + (size_t)KS * KS;

    void *p_esum_syn, *p_esum_sem, *p_cnt_syn, *p_cnt_sem, *p_pair_syn, *p_pair_sem;
    void *p_idx_syn, *p_idx_sem, *p_cn_syn, *p_cn_sem, *p_cl_syn, *p_cl_sem, *p_nsum, *p_loss;
    void *p_maxcn, *p_zbf_syn, *p_zbf_sem, *p_cbf_syn, *p_cbf_sem, *p_cv, *p_ck;
    cudaGetSymbolAddress(&p_esum_syn, g_esum_syn);
    cudaGetSymbolAddress(&p_esum_sem, g_esum_sem);
    cudaGetSymbolAddress(&p_cnt_syn, g_counts_syn);
    cudaGetSymbolAddress(&p_cnt_sem, g_counts_sem);
    cudaGetSymbolAddress(&p_pair_syn, g_pair_syn);
    cudaGetSymbolAddress(&p_pair_sem, g_pair_sem);
    cudaGetSymbolAddress(&p_idx_syn, g_idx_syn);
    cudaGetSymbolAddress(&p_idx_sem, g_idx_sem);
    cudaGetSymbolAddress(&p_cn_syn, g_cnorm_syn);
    cudaGetSymbolAddress(&p_cn_sem, g_cnorm_sem);
    cudaGetSymbolAddress(&p_cl_syn, g_clnew_syn);
    cudaGetSymbolAddress(&p_cl_sem, g_clnew_sem);
    cudaGetSymbolAddress(&p_nsum, g_nsum);
    cudaGetSymbolAddress(&p_loss, g_losspart);
    cudaGetSymbolAddress(&p_maxcn, g_maxcn);
    cudaGetSymbolAddress(&p_zbf_syn, g_zbf_syn);
    cudaGetSymbolAddress(&p_zbf_sem, g_zbf_sem);
    cudaGetSymbolAddress(&p_cbf_syn, g_cbf_syn);
    cudaGetSymbolAddress(&p_cbf_sem, g_cbf_sem);
    cudaGetSymbolAddress(&p_cv, g_cv);
    cudaGetSymbolAddress(&p_ck, g_ck);

    cudaFuncSetAttribute(dist_hmma_kernel,
                         cudaFuncAttributeMaxDynamicSharedMemorySize, SM2_TOTAL);

    // 1) zero scratch
    cudaMemsetAsync(p_esum_syn, 0, (size_t)KS * GD * sizeof(float));
    cudaMemsetAsync(p_esum_sem, 0, (size_t)KM * GD * sizeof(float));
    cudaMemsetAsync(p_cnt_syn, 0, KS * sizeof(float));
    cudaMemsetAsync(p_cnt_sem, 0, KM * sizeof(float));
    cudaMemsetAsync(p_pair_syn, 0, (size_t)KS * KS * sizeof(int));
    cudaMemsetAsync(p_pair_sem, 0, (size_t)KM * KM * sizeof(int));
    cudaMemsetAsync(p_nsum, 0, 2 * sizeof(float));
    cudaMemsetAsync(p_loss, 0, 512 * sizeof(float));
    cudaMemsetAsync(p_maxcn, 0, 2 * sizeof(int));

    // 2) conversions (+ fused codebook norms)
    cvt_z_kernel<<<(GN * GD) / 4096, 256>>>(zre_f, zim_f, (__nv_bfloat16*)p_zbf_syn);
    cvt_z_kernel<<<(GN * GD) / 4096, 256>>>(zre_s, zim_s, (__nv_bfloat16*)p_zbf_sem);
    cvt_cb_norm_kernel<<<KS / 2, 256>>>(cb_syn, (__nv_bfloat16*)p_cbf_syn,
                                        (float*)p_cn_syn, (int*)p_maxcn);
    cvt_cb_norm_kernel<<<KM / 2, 256>>>(cb_sem, (__nv_bfloat16*)p_cbf_sem,
                                        (float*)p_cn_sem, ((int*)p_maxcn) + 1);

    // 3) HMMA approximate distance pass (occupancy 2)
    dist_hmma_kernel<<<NUNITS2, 256, SM2_TOTAL>>>(
        (const __nv_bfloat16*)p_zbf_syn, (const __nv_bfloat16*)p_cbf_syn, (const float*)p_cn_syn,
        (const __nv_bfloat16*)p_zbf_sem, (const __nv_bfloat16*)p_cbf_sem, (const float*)p_cn_sem,
        (float*)p_cv, (int*)p_ck);

    // 4) exact fp32 refinement -> final indices
    refine_kernel<<<(2 * GN) / 8, 256>>>(
        zre_f, zim_f, cb_syn, (const float*)p_cn_syn,
        zre_s, zim_s, cb_sem, (const float*)p_cn_sem,
        (const float*)p_cv, (const int*)p_ck, (const int*)p_maxcn,
        (int*)p_idx_syn, (int*)p_idx_sem);

    // 5) fused per-row scatter + zq + loss
    fuse_row_kernel<<<GN, 128>>>(zre_f, zim_f, (const int*)p_idx_syn, prev_syn, cb_syn,
                                 (float*)p_cnt_syn, (float*)p_esum_syn, (int*)p_pair_syn, KS,
                                 out + OFF_ZQ_SYN, out + OFF_IDX_SYN, (float*)p_loss);
    fuse_row_kernel<<<GN, 128>>>(zre_s, zim_s, (const int*)p_idx_sem, prev_sem, cb_sem,
                                 (float*)p_cnt_sem, (float*)p_esum_sem, (int*)p_pair_sem, KM,
                                 out + OFF_ZQ_SEM, out + OFF_IDX_SEM, (float*)p_loss);

    // 6) cluster size EMA + n
    clnew_kernel<<<KS / 256, 256>>>(cl_syn, (const float*)p_cnt_syn,
                                    (float*)p_cl_syn, (float*)p_nsum, KS);
    clnew_kernel<<<KM / 256, 256>>>(cl_sem, (const float*)p_cnt_sem,
                                    (float*)p_cl_sem, ((float*)p_nsum) + 1, KM);

    // 7) codebook EMA update
    cbnew_kernel<<<(KS * GD) / 256, 256>>>(avg_syn, (const float*)p_esum_syn,
                                           (const float*)p_cl_syn, (const float*)p_nsum,
                                           out + OFF_CB_SYN, KS);
    cbnew_kernel<<<(KM * GD) / 256, 256>>>(avg_sem, (const float*)p_esum_sem,
                                           (const float*)p_cl_sem, ((const float*)p_nsum) + 1,
                                           out + OFF_CB_SEM, KM);

    // 8) loss finalize
    finalize_loss_kernel<<<1, 256>>>((const float*)p_loss, out + OFF_LOSS);

    // 9) adjacency transform
    {
        size_t tot = (size_t)KS * KS;
        adj_kernel<<<(unsigned)(tot / 1024), 256>>>(adj_syn, (const int*)p_pair_syn,
                                                    out + OFF_ADJ_SYN, tot);
    }
    {
        size_t tot = (size_t)KM * KM;
        adj_kernel<<<(unsigned)(tot / 1024), 256>>>(adj_sem, (const int*)p_pair_sem,
                                                    out + OFF_ADJ_SEM, tot);
    }
    (void)in_sizes; (void)n_in; (void)out_size;
}

// round 13
// speedup vs baseline: 1.1681x; 1.0936x over previous
#include <cuda_runtime.h>
#include <cuda_bf16.h>
#include <math.h>
#include <float.h>
#include <stdint.h>

// Problem constants
#define GN   32768
#define GLD  256
#define GD   512
#define KS   1024
#define KM   4096
// 64-row units: 512 syn + 2048 sem (512 row-tiles x 4 k-chunks)
#define NUNITS2 2560

// ---------------- scratch (static __device__, no allocation) ----------------
static __device__ __align__(16) float g_esum_syn[KS * GD];
static __device__ __align__(16) float g_esum_sem[KM * GD];
static __device__ float g_counts_syn[KS];
static __device__ float g_counts_sem[KM];
static __device__ int   g_pair_syn[(size_t)KS * KS];   // self-draining (adj_sparse)
static __device__ int   g_pair_sem[(size_t)KM * KM];   // self-draining (adj_sparse)
static __device__ int   g_idx_syn[GN];
static __device__ int   g_idx_sem[GN];
static __device__ float g_cnorm_syn[KS];
static __device__ float g_cnorm_sem[KM];
static __device__ float g_clnew_syn[KS];
static __device__ float g_clnew_sem[KM];
static __device__ float g_nsum[2];
static __device__ float g_losspart[512];
static __device__ int   g_maxcn[2];   // float-as-int max of squared code norms
// bf16 copies (16B-aligned for uint4 access)
static __device__ __align__(16) __nv_bfloat16 g_zbf_syn[(size_t)GN * GD];
static __device__ __align__(16) __nv_bfloat16 g_zbf_sem[(size_t)GN * GD];
static __device__ __align__(16) __nv_bfloat16 g_cbf_syn[(size_t)KS * GD];
static __device__ __align__(16) __nv_bfloat16 g_cbf_sem[(size_t)KM * GD];
// candidates: per (unit): 64 rows x 32 slots = 2048 entries
static __device__ float g_cv[(size_t)NUNITS2 * 2048];
static __device__ int   g_ck[(size_t)NUNITS2 * 2048];

// ---------------- PTX helpers (arch-agnostic: ldmatrix + mma.sync) ----------
__device__ __forceinline__ uint32_t smem_u32(const void* p) {
    uint32_t a;
    asm("{ .reg .u64 t; cvta.to.shared.u64 t, %1; cvt.u32.u64 %0, t; }" : "=r"(a) : "l"(p));
    return a;
}
__device__ __forceinline__ void ldsm4(uint32_t& r0, uint32_t& r1, uint32_t& r2, uint32_t& r3,
                                      uint32_t addr) {
    asm volatile("ldmatrix.sync.aligned.m8n8.x4.shared.b16 {%0,%1,%2,%3}, [%4];"
                 : "=r"(r0), "=r"(r1), "=r"(r2), "=r"(r3) : "r"(addr));
}
__device__ __forceinline__ void mma_bf16(float* d, const uint32_t* a, uint32_t b0, uint32_t b1) {
    asm volatile("mma.sync.aligned.m16n8k16.row.col.f32.bf16.bf16.f32 "
                 "{%0,%1,%2,%3}, {%4,%5,%6,%7}, {%8,%9}, {%0,%1,%2,%3};"
                 : "+f"(d[0]), "+f"(d[1]), "+f"(d[2]), "+f"(d[3])
                 : "r"(a[0]), "r"(a[1]), "r"(a[2]), "r"(a[3]), "r"(b0), "r"(b1));
}
__device__ __forceinline__ void red_add_v4(float* gptr, float4 v) {
    asm volatile("red.global.add.v4.f32 [%0], {%1, %2, %3, %4};"
                 :: "l"(gptr), "f"(v.x), "f"(v.y), "f"(v.z), "f"(v.w) : "memory");
}

// ---------------- generic helpers ----------------
__device__ __forceinline__ float blk_reduce_256(float v) {
    __shared__ float sh[8];
    int lane = threadIdx.x & 31, w = threadIdx.x >> 5;
#pragma unroll
    for (int o = 16; o; o >>= 1) v += __shfl_down_sync(0xffffffffu, v, o);
    if (lane == 0) sh[w] = v;
    __syncthreads();
    if (w == 0) {
        v = (lane < 8) ? sh[lane] : 0.f;
#pragma unroll
        for (int o = 4; o; o >>= 1) v += __shfl_down_sync(0xffffffffu, v, o);
    }
    return v;
}

// ---------------- conversions ----------------
__global__ void cvt_z_kernel(const float* __restrict__ re, const float* __restrict__ im,
                             __nv_bfloat16* __restrict__ out) {
#pragma unroll
    for (int j = 0; j < 4; j++) {
        size_t e = (size_t)blockIdx.x * 4096 + j * 1024 + threadIdx.x * 4;
        int n = (int)(e >> 9), d = (int)(e & 511);
        const float* s = (d < GLD) ? re + (size_t)n * GLD + d
                                   : im + (size_t)n * GLD + (d - GLD);
        float4 v = *(const float4*)s;
        __nv_bfloat162 a = __floats2bfloat162_rn(v.x, v.y);
        __nv_bfloat162 b = __floats2bfloat162_rn(v.z, v.w);
        ((__nv_bfloat162*)(out + e))[0] = a;
        ((__nv_bfloat162*)(out + e))[1] = b;
    }
}

// fused codebook convert + per-row squared norms + max
__global__ void cvt_cb_norm_kernel(const float* __restrict__ cb, __nv_bfloat16* __restrict__ out,
                                   float* __restrict__ norms, int* __restrict__ mx) {
    __shared__ float sh[8];
    int t = threadIdx.x, lane = t & 31, w = t >> 5;
    size_t e = ((size_t)blockIdx.x * 256 + t) * 4;
    float4 v = *(const float4*)(cb + e);
    __nv_bfloat162 a = __floats2bfloat162_rn(v.x, v.y);
    __nv_bfloat162 b = __floats2bfloat162_rn(v.z, v.w);
    ((__nv_bfloat162*)(out + e))[0] = a;
    ((__nv_bfloat162*)(out + e))[1] = b;
    float s = v.x * v.x + v.y * v.y + v.z * v.z + v.w * v.w;
#pragma unroll
    for (int o = 16; o; o >>= 1) s += __shfl_xor_sync(0xffffffffu, s, o);
    if (lane == 0) sh[w] = s;
    __syncthreads();
    if (t == 0) {
        float n0 = sh[0] + sh[1] + sh[2] + sh[3];
        norms[blockIdx.x * 2] = n0;
        atomicMax(mx, __float_as_int(n0));
    } else if (t == 128) {
        float n1 = sh[4] + sh[5] + sh[6] + sh[7];
        norms[blockIdx.x * 2 + 1] = n1;
        atomicMax(mx, __float_as_int(n1));
    }
}

// ---------------- HMMA bf16 distance pass (64-row units, occupancy 2) ------
#define SM2_Z      0
#define SM2_C      66560
#define SM2_CN     (66560 + 18432)            // 84992
#define SM2_TOTAL  (SM2_CN + 4096)            // 89088
#define SM2_SV     SM2_Z
#define SM2_SK     (SM2_Z + 8192)

__global__ __launch_bounds__(256, 2) void dist_hmma_kernel(
    const __nv_bfloat16* __restrict__ zbfA, const __nv_bfloat16* __restrict__ cbfA,
    const float* __restrict__ cnA,
    const __nv_bfloat16* __restrict__ zbfB, const __nv_bfloat16* __restrict__ cbfB,
    const float* __restrict__ cnB,
    float* __restrict__ cvout, int* __restrict__ ckout)
{
    extern __shared__ __align__(16) char smem[];
    char* sZ = smem + SM2_Z;
    char* sC = smem + SM2_C;
    float* sCN = (float*)(smem + SM2_CN);
    const uint32_t sbase = smem_u32(smem);

    const int tid = threadIdx.x, wid = tid >> 5, lane = tid & 31;
    const int u = blockIdx.x;

    const __nv_bfloat16 *zsrc, *csrc;
    const float* cn;
    int rowBase, kBase;
    if (u < 512) {
        zsrc = zbfA; csrc = cbfA; cn = cnA; rowBase = u * 64; kBase = 0;
    } else {
        int v = u - 512;
        zsrc = zbfB; csrc = cbfB; cn = cnB;
        rowBase = (v >> 2) * 64; kBase = (v & 3) * 1024;
    }

    // load Z tile: 64 rows x 512 bf16
#pragma unroll
    for (int i = 0; i < 16; i++) {
        int c = tid + 256 * i;       // 16B chunk id, 0..4095
        int r = c >> 6, c8 = c & 63;
        uint4 v = *(const uint4*)(zsrc + (((size_t)(rowBase + r)) << 9) + c8 * 8);
        *(uint4*)(sZ + r * 1040 + c8 * 16) = v;
    }
    // load cn table: 1024 floats
#pragma unroll
    for (int j = 0; j < 4; j++) {
        int idx = tid + 256 * j;
        sCN[idx] = cn[kBase + idx];
    }

    const int wm = wid >> 2, wn = wid & 3;
    const uint32_t zaddr0 = sbase + SM2_Z +
        (uint32_t)((wm * 32 + (lane & 15)) * 1040 + (lane >> 4) * 16);
    const uint32_t caddr0 = sbase + SM2_C +
        (uint32_t)((wn * 32 + ((lane >> 4) << 3) + (lane & 7)) * 144 + ((lane >> 3) & 1) * 16);

    float tv[4][2]; int tk[4][2];
#pragma unroll
    for (int i = 0; i < 4; i++)
#pragma unroll
        for (int s = 0; s < 2; s++) { tv[i][s] = FLT_MAX; tk[i][s] = 0; }

    float acc[2][4][4];
#pragma unroll
    for (int mt = 0; mt < 2; mt++)
#pragma unroll
        for (int nt = 0; nt < 4; nt++)
#pragma unroll
            for (int q = 0; q < 4; q++) acc[mt][nt][q] = 0.f;

#define LDGC(pf, cc) do { \
        int _t = (cc) >> 3, _dc = (cc) & 7; \
        _Pragma("unroll") \
        for (int _j = 0; _j < 4; _j++) { \
            int _id = tid + 256 * _j; int _r = _id >> 3, _c8 = _id & 7; \
            (pf)[_j] = *(const uint4*)(csrc + (((size_t)(kBase + _t * 128 + _r)) << 9) \
                                       + _dc * 64 + _c8 * 8); \
        } \
    } while (0)

    uint4 pf[4];
    LDGC(pf, 0);

    for (int c = 0; c < 64; c++) {
        __syncthreads();
#pragma unroll
        for (int j = 0; j < 4; j++) {
            int id = tid + 256 * j, r = id >> 3, c8 = id & 7;
            *(uint4*)(sC + r * 144 + c8 * 16) = pf[j];
        }
        if (c + 1 < 64) LDGC(pf, c + 1);
        __syncthreads();

        const int dc = c & 7;
#pragma unroll
        for (int ks = 0; ks < 4; ks++) {
            uint32_t b[8];
            ldsm4(b[0], b[1], b[2], b[3], caddr0 + ks * 32);
            ldsm4(b[4], b[5], b[6], b[7], caddr0 + 16 * 144 + ks * 32);
            uint32_t a[2][4];
#pragma unroll
            for (int mt = 0; mt < 2; mt++)
                ldsm4(a[mt][0], a[mt][1], a[mt][2], a[mt][3],
                      zaddr0 + (uint32_t)(mt * 16 * 1040 + (dc * 64 + ks * 16) * 2));
#pragma unroll
            for (int mt = 0; mt < 2; mt++)
#pragma unroll
                for (int nt = 0; nt < 4; nt++)
                    mma_bf16(acc[mt][nt], a[mt], b[(nt >> 1) * 4 + (nt & 1) * 2],
                             b[(nt >> 1) * 4 + (nt & 1) * 2 + 1]);
        }

        if (dc == 7) {
            const int tbase = (c >> 3) * 128;
#pragma unroll
            for (int mt = 0; mt < 2; mt++)
#pragma unroll
                for (int half = 0; half < 2; half++) {
                    int i = mt * 2 + half;
#pragma unroll
                    for (int nt = 0; nt < 4; nt++)
#pragma unroll
                        for (int cc2 = 0; cc2 < 2; cc2++) {
                            int col = wn * 32 + nt * 8 + (lane & 3) * 2 + cc2;
                            float s = acc[mt][nt][half * 2 + cc2];
                            float v = fmaf(-2.f, s, sCN[tbase + col]);
                            int k = kBase + tbase + col;
                            if (v < tv[i][0]) {
                                tv[i][1] = tv[i][0]; tk[i][1] = tk[i][0];
                                tv[i][0] = v; tk[i][0] = k;
                            } else if (v < tv[i][1]) {
                                tv[i][1] = v; tk[i][1] = k;
                            }
                        }
                }
#pragma unroll
            for (int mt = 0; mt < 2; mt++)
#pragma unroll
                for (int nt = 0; nt < 4; nt++)
#pragma unroll
                    for (int q = 0; q < 4; q++) acc[mt][nt][q] = 0.f;
        }
    }

    // stage candidates in SMEM (reuse Z area), then coalesced store
    __syncthreads();
    float* sv = (float*)(smem + SM2_SV);
    int*   sk = (int*)(smem + SM2_SK);
#pragma unroll
    for (int i = 0; i < 4; i++) {
        int r = wm * 32 + (i >> 1) * 16 + (i & 1) * 8 + (lane >> 2);
        int slot0 = wn * 8 + (lane & 3) * 2;
#pragma unroll
        for (int s = 0; s < 2; s++) {
            sv[r * 32 + slot0 + s] = tv[i][s];
            sk[r * 32 + slot0 + s] = tk[i][s];
        }
    }
    __syncthreads();
#pragma unroll
    for (int j = 0; j < 8; j++) {
        int idx = tid + 256 * j;
        cvout[(size_t)u * 2048 + idx] = sv[idx];
        ckout[(size_t)u * 2048 + idx] = sk[idx];
    }
#undef LDGC
}

// ---------------- exact fp32 refinement (parallel candidate preload) -------
__global__ __launch_bounds__(256) void refine_kernel(
    const float* __restrict__ zreA, const float* __restrict__ zimA,
    const float* __restrict__ cbA, const float* __restrict__ cnA,
    const float* __restrict__ zreB, const float* __restrict__ zimB,
    const float* __restrict__ cbB, const float* __restrict__ cnB,
    const float* __restrict__ cv, const int* __restrict__ ck,
    const int* __restrict__ maxcn,
    int* __restrict__ idxA, int* __restrict__ idxB)
{
    int wid = threadIdx.x >> 5, lane = threadIdx.x & 31;
    int gw = blockIdx.x * 8 + wid;
    int n = gw >> 1, cbk = gw & 1;
    const float *zre, *zim, *cb, *cn;
    int* idxo;
    int cnt;
    size_t base;
    if (cbk == 0) {
        zre = zreA; zim = zimA; cb = cbA; cn = cnA; idxo = idxA;
        cnt = 32;
        base = (size_t)(n >> 6) * 2048 + (size_t)(n & 63) * 32;
    } else {
        zre = zreB; zim = zimB; cb = cbB; cn = cnB; idxo = idxB;
        cnt = 128;
        base = (size_t)(512 + (n >> 6) * 4) * 2048 + (size_t)(n & 63) * 32;
    }

    float candv[4]; int candk[4];
    const int nj = cnt >> 5;
#pragma unroll
    for (int j = 0; j < 4; j++) {
        if (j < nj) {
            size_t a = base + (size_t)j * 2048 + lane;
            candv[j] = cv[a];
            candk[j] = ck[a];
        } else { candv[j] = FLT_MAX; candk[j] = 0x7fffffff; }
    }

    float zr[16];
    float zn2 = 0.f;
#pragma unroll
    for (int j = 0; j < 16; j++) {
        int d = lane + 32 * j;
        float z = (d < GLD) ? zre[(size_t)n * GLD + d] : zim[(size_t)n * GLD + d - GLD];
        zr[j] = z;
        zn2 = fmaf(z, z, zn2);
    }
#pragma unroll
    for (int o = 16; o; o >>= 1) zn2 += __shfl_xor_sync(0xffffffffu, zn2, o);

    float vb = fminf(fminf(candv[0], candv[1]), fminf(candv[2], candv[3]));
#pragma unroll
    for (int o = 16; o; o >>= 1) vb = fminf(vb, __shfl_xor_sync(0xffffffffu, vb, o));

    float maxc2 = __int_as_float(maxcn[cbk]);
    float vlim = vb + 0.03125f * sqrtf(zn2 * maxc2) + 0.125f;

    float bd = FLT_MAX; int bk = 0x7fffffff;
    for (int i = 0; i < cnt; i++) {
        float v = __shfl_sync(0xffffffffu, candv[i >> 5], i & 31);
        if (v <= vlim) {
            int k = __shfl_sync(0xffffffffu, candk[i >> 5], i & 31);
            const float* crow = cb + (size_t)k * GD;
            float s = 0.f;
#pragma unroll
            for (int j = 0; j < 16; j++) s = fmaf(zr[j], crow[lane + 32 * j], s);
#pragma unroll
            for (int o = 16; o; o >>= 1) s += __shfl_xor_sync(0xffffffffu, s, o);
            float d = fmaf(-2.f, s, cn[k]);
            if (d < bd || (d == bd && k < bk)) { bd = d; bk = k; }
        }
    }
    if (lane == 0) idxo[n] = bk;
}

// ---- fused per-row: counts/pair scatter + esum scatter + zq write + loss ----
__global__ __launch_bounds__(128) void fuse_row_kernel(
    const float* __restrict__ zre, const float* __restrict__ zim,
    const int* __restrict__ idx, const int* __restrict__ prev,
    const float* __restrict__ cb,
    float* __restrict__ counts, float* __restrict__ esum, int* __restrict__ pair, int K,
    float* __restrict__ zq, float* __restrict__ idxf, float* __restrict__ lossPart)
{
    __shared__ float sh[4];
    int n = blockIdx.x, t = threadIdx.x;
    int lane = t & 31, w = t >> 5;
    int i = idx[n];
    if (t == 0) {
        atomicAdd(&counts[i], 1.f);
        atomicAdd(&pair[(size_t)prev[n] * K + i], 1);
        idxf[n] = (float)i;
    }
    int d = t * 4;
    const float* zsrc = (d < GLD) ? zre + (size_t)n * GLD + d
                                  : zim + (size_t)n * GLD + (d - GLD);
    float4 z = *(const float4*)zsrc;
    float4 q = *(const float4*)(cb + (size_t)i * GD + d);
    *(float4*)(zq + (size_t)n * GD + d) = q;
    float dx = q.x - z.x, dy = q.y - z.y, dz = q.z - z.z, dw = q.w - z.w;
    float s = dx * dx + dy * dy + dz * dz + dw * dw;
    red_add_v4(esum + (size_t)i * GD + d, z);
#pragma unroll
    for (int o = 16; o; o >>= 1) s += __shfl_down_sync(0xffffffffu, s, o);
    if (lane == 0) sh[w] = s;
    __syncthreads();
    if (t == 0) atomicAdd(&lossPart[n & 511], sh[0] + sh[1] + sh[2] + sh[3]);
}

// ---------------- cluster_size EMA + n reduction ----------------
__global__ void clnew_kernel(const float* __restrict__ cl, const float* __restrict__ counts,
                             float* __restrict__ clnew, float* __restrict__ nsum, int K)
{
    int k = blockIdx.x * 256 + threadIdx.x;
    float v = 0.f;
    if (k < K) {
        v = cl[k] * 0.99f + 0.01f * counts[k];
        clnew[k] = v;
    }
    v = blk_reduce_256(v);
    if (threadIdx.x == 0) atomicAdd(nsum, v);
}

// ---------------- codebook EMA update ----------------
__global__ void cbnew_kernel(const float* __restrict__ avg, const float* __restrict__ esum,
                             const float* __restrict__ clnew, const float* __restrict__ nsum,
                             float* __restrict__ out, int K)
{
    size_t idx = (size_t)blockIdx.x * 256 + threadIdx.x;
    int k = (int)(idx >> 9);
    float n = *nsum;
    float cs = (clnew[k] + 1e-6f) / (n + (float)K * 1e-6f) * n;
    float a = avg[idx] * 0.99f + 0.01f * esum[idx];
    out[idx] = a / cs;
}

__global__ void finalize_loss_kernel(const float* __restrict__ lacc, float* __restrict__ out) {
    __shared__ float sh[8];
    int t = threadIdx.x, lane = t & 31, w = t >> 5;
    float s = lacc[t] + lacc[t + 256];
#pragma unroll
    for (int o = 16; o; o >>= 1) s += __shfl_down_sync(0xffffffffu, s, o);
    if (lane == 0) sh[w] = s;
    __syncthreads();
    if (t == 0) {
        float v = 0.f;
#pragma unroll
        for (int j = 0; j < 8; j++) v += sh[j];
        out[0] = 1.25f * v / 16777216.f;
    }
}

// ---------------- sparse adjacency update ----------------
// Touched pairs only; drains pair counts back to zero (replay-safe).
// out was pre-filled with adj via cudaMemcpyAsync.
__global__ void adj_sparse_kernel(const int* __restrict__ prev, const int* __restrict__ idxv,
                                  int K, int* __restrict__ pair,
                                  const float* __restrict__ adj, float* __restrict__ out)
{
    int n = blockIdx.x * 256 + threadIdx.x;
    size_t p = (size_t)prev[n] * K + idxv[n];
    int c = atomicExch(&pair[p], 0);
    if (c > 0) {
        float pw = __powf(0.99f, (float)c);
        out[p] = fmaf(adj[p], pw, (1.f - pw) * 100.f);
    }
}

// ---------------- launch ----------------
extern "C" void kernel_launch(void* const* d_in, const int* in_sizes, int n_in,
                              void* d_out, int out_size)
{
    const float* zre_f = (const float*)d_in[0];
    const float* zim_f = (const float*)d_in[1];
    const float* zre_s = (const float*)d_in[2];
    const float* zim_s = (const float*)d_in[3];
    const int*   prev_syn = (const int*)d_in[4];
    const int*   prev_sem = (const int*)d_in[5];
    const float* cb_syn = (const float*)d_in[6];
    const float* cb_sem = (const float*)d_in[7];
    const float* cl_syn = (const float*)d_in[8];
    const float* avg_syn = (const float*)d_in[9];
    const float* cl_sem = (const float*)d_in[10];
    const float* avg_sem = (const float*)d_in[11];
    const float* adj_syn = (const float*)d_in[12];
    const float* adj_sem = (const float*)d_in[13];

    float* out = (float*)d_out;
    const size_t OFF_ZQ_SYN = 0;
    const size_t OFF_ZQ_SEM = OFF_ZQ_SYN + (size_t)GN * GD;
    const size_t OFF_LOSS   = OFF_ZQ_SEM + (size_t)GN * GD;
    const size_t OFF_IDX_SYN = OFF_LOSS + 1;
    const size_t OFF_IDX_SEM = OFF_IDX_SYN + GN;
    const size_t OFF_CB_SYN  = OFF_IDX_SEM + GN;
    const size_t OFF_CB_SEM  = OFF_CB_SYN + (size_t)KS * GD;
    const size_t OFF_ADJ_SYN = OFF_CB_SEM + (size_t)KM * GD;
    const size_t OFF_ADJ_SEM = OFF_ADJ_SYN + (size_t)KS * KS;

    void *p_esum_syn, *p_esum_sem, *p_cnt_syn, *p_cnt_sem, *p_pair_syn, *p_pair_sem;
    void *p_idx_syn, *p_idx_sem, *p_cn_syn, *p_cn_sem, *p_cl_syn, *p_cl_sem, *p_nsum, *p_loss;
    void *p_maxcn, *p_zbf_syn, *p_zbf_sem, *p_cbf_syn, *p_cbf_sem, *p_cv, *p_ck;
    cudaGetSymbolAddress(&p_esum_syn, g_esum_syn);
    cudaGetSymbolAddress(&p_esum_sem, g_esum_sem);
    cudaGetSymbolAddress(&p_cnt_syn, g_counts_syn);
    cudaGetSymbolAddress(&p_cnt_sem, g_counts_sem);
    cudaGetSymbolAddress(&p_pair_syn, g_pair_syn);
    cudaGetSymbolAddress(&p_pair_sem, g_pair_sem);
    cudaGetSymbolAddress(&p_idx_syn, g_idx_syn);
    cudaGetSymbolAddress(&p_idx_sem, g_idx_sem);
    cudaGetSymbolAddress(&p_cn_syn, g_cnorm_syn);
    cudaGetSymbolAddress(&p_cn_sem, g_cnorm_sem);
    cudaGetSymbolAddress(&p_cl_syn, g_clnew_syn);
    cudaGetSymbolAddress(&p_cl_sem, g_clnew_sem);
    cudaGetSymbolAddress(&p_nsum, g_nsum);
    cudaGetSymbolAddress(&p_loss, g_losspart);
    cudaGetSymbolAddress(&p_maxcn, g_maxcn);
    cudaGetSymbolAddress(&p_zbf_syn, g_zbf_syn);
    cudaGetSymbolAddress(&p_zbf_sem, g_zbf_sem);
    cudaGetSymbolAddress(&p_cbf_syn, g_cbf_syn);
    cudaGetSymbolAddress(&p_cbf_sem, g_cbf_sem);
    cudaGetSymbolAddress(&p_cv, g_cv);
    cudaGetSymbolAddress(&p_ck, g_ck);

    cudaFuncSetAttribute(dist_hmma_kernel,
                         cudaFuncAttributeMaxDynamicSharedMemorySize, SM2_TOTAL);

    // 1) zero scratch (pair arrays are self-draining via adj_sparse; no memset)
    cudaMemsetAsync(p_esum_syn, 0, (size_t)KS * GD * sizeof(float));
    cudaMemsetAsync(p_esum_sem, 0, (size_t)KM * GD * sizeof(float));
    cudaMemsetAsync(p_cnt_syn, 0, KS * sizeof(float));
    cudaMemsetAsync(p_cnt_sem, 0, KM * sizeof(float));
    cudaMemsetAsync(p_nsum, 0, 2 * sizeof(float));
    cudaMemsetAsync(p_loss, 0, 512 * sizeof(float));
    cudaMemsetAsync(p_maxcn, 0, 2 * sizeof(int));

    // 2) pre-fill adjacency outputs with pass-through values
    cudaMemcpyAsync(out + OFF_ADJ_SYN, adj_syn, (size_t)KS * KS * sizeof(float),
                    cudaMemcpyDeviceToDevice);
    cudaMemcpyAsync(out + OFF_ADJ_SEM, adj_sem, (size_t)KM * KM * sizeof(float),
                    cudaMemcpyDeviceToDevice);

    // 3) conversions (+ fused codebook norms)
    cvt_z_kernel<<<(GN * GD) / 4096, 256>>>(zre_f, zim_f, (__nv_bfloat16*)p_zbf_syn);
    cvt_z_kernel<<<(GN * GD) / 4096, 256>>>(zre_s, zim_s, (__nv_bfloat16*)p_zbf_sem);
    cvt_cb_norm_kernel<<<KS / 2, 256>>>(cb_syn, (__nv_bfloat16*)p_cbf_syn,
                                        (float*)p_cn_syn, (int*)p_maxcn);
    cvt_cb_norm_kernel<<<KM / 2, 256>>>(cb_sem, (__nv_bfloat16*)p_cbf_sem,
                                        (float*)p_cn_sem, ((int*)p_maxcn) + 1);

    // 4) HMMA approximate distance pass (occupancy 2)
    dist_hmma_kernel<<<NUNITS2, 256, SM2_TOTAL>>>(
        (const __nv_bfloat16*)p_zbf_syn, (const __nv_bfloat16*)p_cbf_syn, (const float*)p_cn_syn,
        (const __nv_bfloat16*)p_zbf_sem, (const __nv_bfloat16*)p_cbf_sem, (const float*)p_cn_sem,
        (float*)p_cv, (int*)p_ck);

    // 5) exact fp32 refinement -> final indices
    refine_kernel<<<(2 * GN) / 8, 256>>>(
        zre_f, zim_f, cb_syn, (const float*)p_cn_syn,
        zre_s, zim_s, cb_sem, (const float*)p_cn_sem,
        (const float*)p_cv, (const int*)p_ck, (const int*)p_maxcn,
        (int*)p_idx_syn, (int*)p_idx_sem);

    // 6) fused per-row scatter + zq + loss (vector red for esum)
    fuse_row_kernel<<<GN, 128>>>(zre_f, zim_f, (const int*)p_idx_syn, prev_syn, cb_syn,
                                 (float*)p_cnt_syn, (float*)p_esum_syn, (int*)p_pair_syn, KS,
                                 out + OFF_ZQ_SYN, out + OFF_IDX_SYN, (float*)p_loss);
    fuse_row_kernel<<<GN, 128>>>(zre_s, zim_s, (const int*)p_idx_sem, prev_sem, cb_sem,
                                 (float*)p_cnt_sem, (float*)p_esum_sem, (int*)p_pair_sem, KM,
                                 out + OFF_ZQ_SEM, out + OFF_IDX_SEM, (float*)p_loss);

    // 7) cluster size EMA + n
    clnew_kernel<<<KS / 256, 256>>>(cl_syn, (const float*)p_cnt_syn,
                                    (float*)p_cl_syn, (float*)p_nsum, KS);
    clnew_kernel<<<KM / 256, 256>>>(cl_sem, (const float*)p_cnt_sem,
                                    (float*)p_cl_sem, ((float*)p_nsum) + 1, KM);

    // 8) codebook EMA update
    cbnew_kernel<<<(KS * GD) / 256, 256>>>(avg_syn, (const float*)p_esum_syn,
                                           (const float*)p_cl_syn, (const float*)p_nsum,
                                           out + OFF_CB_SYN, KS);
    cbnew_kernel<<<(KM * GD) / 256, 256>>>(avg_sem, (const float*)p_esum_sem,
                                           (const float*)p_cl_sem, ((const float*)p_nsum) + 1,
                                           out + OFF_CB_SEM, KM);

    // 9) loss finalize
    finalize_loss_kernel<<<1, 256>>>((const float*)p_loss, out + OFF_LOSS);

    // 10) sparse adjacency updates (drain pair counts)
    adj_sparse_kernel<<<GN / 256, 256>>>(prev_syn, (const int*)p_idx_syn, KS,
                                         (int*)p_pair_syn, adj_syn, out + OFF_ADJ_SYN);
    adj_sparse_kernel<<<GN / 256, 256>>>(prev_sem, (const int*)p_idx_sem, KM,
                                         (int*)p_pair_sem, adj_sem, out + OFF_ADJ_SEM);
    (void)in_sizes; (void)n_in; (void)out_size;
}

// round 14
// speedup vs baseline: 1.1753x; 1.0061x over previous
#include <cuda_runtime.h>
#include <cuda_bf16.h>
#include <math.h>
#include <float.h>
#include <stdint.h>

// Problem constants
#define GN   32768
#define GLD  256
#define GD   512
#define KS   1024
#define KM   4096
// 64-row units: 512 syn + 2048 sem (512 row-tiles x 4 k-chunks)
#define NUNITS2 2560

// ---------------- scratch (static __device__, no allocation) ----------------
static __device__ __align__(16) float g_esum_syn[KS * GD];
static __device__ __align__(16) float g_esum_sem[KM * GD];
static __device__ float g_counts_syn[KS];
static __device__ float g_counts_sem[KM];
static __device__ int   g_pair_syn[(size_t)KS * KS];   // self-draining (adj_sparse)
static __device__ int   g_pair_sem[(size_t)KM * KM];   // self-draining (adj_sparse)
static __device__ int   g_idx_syn[GN];
static __device__ int   g_idx_sem[GN];
static __device__ float g_cnorm_syn[KS];
static __device__ float g_cnorm_sem[KM];
static __device__ float g_clnew_syn[KS];
static __device__ float g_clnew_sem[KM];
static __device__ float g_nsum[2];
static __device__ float g_losspart[512];
static __device__ int   g_maxcn[2];   // float-as-int max of squared code norms
// bf16 copies (16B-aligned for uint4 access)
static __device__ __align__(16) __nv_bfloat16 g_zbf_syn[(size_t)GN * GD];
static __device__ __align__(16) __nv_bfloat16 g_zbf_sem[(size_t)GN * GD];
static __device__ __align__(16) __nv_bfloat16 g_cbf_syn[(size_t)KS * GD];
static __device__ __align__(16) __nv_bfloat16 g_cbf_sem[(size_t)KM * GD];
// candidates: per (unit): 64 rows x 32 slots = 2048 entries
static __device__ float g_cv[(size_t)NUNITS2 * 2048];
static __device__ int   g_ck[(size_t)NUNITS2 * 2048];

// ---------------- PTX helpers (arch-agnostic: ldmatrix + mma.sync) ----------
__device__ __forceinline__ uint32_t smem_u32(const void* p) {
    uint32_t a;
    asm("{ .reg .u64 t; cvta.to.shared.u64 t, %1; cvt.u32.u64 %0, t; }" : "=r"(a) : "l"(p));
    return a;
}
__device__ __forceinline__ void ldsm4(uint32_t& r0, uint32_t& r1, uint32_t& r2, uint32_t& r3,
                                      uint32_t addr) {
    asm volatile("ldmatrix.sync.aligned.m8n8.x4.shared.b16 {%0,%1,%2,%3}, [%4];"
                 : "=r"(r0), "=r"(r1), "=r"(r2), "=r"(r3) : "r"(addr));
}
__device__ __forceinline__ void mma_bf16(float* d, const uint32_t* a, uint32_t b0, uint32_t b1) {
    asm volatile("mma.sync.aligned.m16n8k16.row.col.f32.bf16.bf16.f32 "
                 "{%0,%1,%2,%3}, {%4,%5,%6,%7}, {%8,%9}, {%0,%1,%2,%3};"
                 : "+f"(d[0]), "+f"(d[1]), "+f"(d[2]), "+f"(d[3])
                 : "r"(a[0]), "r"(a[1]), "r"(a[2]), "r"(a[3]), "r"(b0), "r"(b1));
}
__device__ __forceinline__ void red_add_v4(float* gptr, float4 v) {
    asm volatile("red.global.add.v4.f32 [%0], {%1, %2, %3, %4};"
                 :: "l"(gptr), "f"(v.x), "f"(v.y), "f"(v.z), "f"(v.w) : "memory");
}

// ---------------- generic helpers ----------------
__device__ __forceinline__ float blk_reduce_256(float v) {
    __shared__ float sh[8];
    int lane = threadIdx.x & 31, w = threadIdx.x >> 5;
#pragma unroll
    for (int o = 16; o; o >>= 1) v += __shfl_down_sync(0xffffffffu, v, o);
    if (lane == 0) sh[w] = v;
    __syncthreads();
    if (w == 0) {
        v = (lane < 8) ? sh[lane] : 0.f;
#pragma unroll
        for (int o = 4; o; o >>= 1) v += __shfl_down_sync(0xffffffffu, v, o);
    }
    return v;
}

// ---------------- conversions ----------------
__global__ void cvt_z_kernel(const float* __restrict__ re, const float* __restrict__ im,
                             __nv_bfloat16* __restrict__ out) {
#pragma unroll
    for (int j = 0; j < 4; j++) {
        size_t e = (size_t)blockIdx.x * 4096 + j * 1024 + threadIdx.x * 4;
        int n = (int)(e >> 9), d = (int)(e & 511);
        const float* s = (d < GLD) ? re + (size_t)n * GLD + d
                                   : im + (size_t)n * GLD + (d - GLD);
        float4 v = *(const float4*)s;
        __nv_bfloat162 a = __floats2bfloat162_rn(v.x, v.y);
        __nv_bfloat162 b = __floats2bfloat162_rn(v.z, v.w);
        ((__nv_bfloat162*)(out + e))[0] = a;
        ((__nv_bfloat162*)(out + e))[1] = b;
    }
}

// fused codebook convert + per-row squared norms + max
__global__ void cvt_cb_norm_kernel(const float* __restrict__ cb, __nv_bfloat16* __restrict__ out,
                                   float* __restrict__ norms, int* __restrict__ mx) {
    __shared__ float sh[8];
    int t = threadIdx.x, lane = t & 31, w = t >> 5;
    size_t e = ((size_t)blockIdx.x * 256 + t) * 4;
    float4 v = *(const float4*)(cb + e);
    __nv_bfloat162 a = __floats2bfloat162_rn(v.x, v.y);
    __nv_bfloat162 b = __floats2bfloat162_rn(v.z, v.w);
    ((__nv_bfloat162*)(out + e))[0] = a;
    ((__nv_bfloat162*)(out + e))[1] = b;
    float s = v.x * v.x + v.y * v.y + v.z * v.z + v.w * v.w;
#pragma unroll
    for (int o = 16; o; o >>= 1) s += __shfl_xor_sync(0xffffffffu, s, o);
    if (lane == 0) sh[w] = s;
    __syncthreads();
    if (t == 0) {
        float n0 = sh[0] + sh[1] + sh[2] + sh[3];
        norms[blockIdx.x * 2] = n0;
        atomicMax(mx, __float_as_int(n0));
    } else if (t == 128) {
        float n1 = sh[4] + sh[5] + sh[6] + sh[7];
        norms[blockIdx.x * 2 + 1] = n1;
        atomicMax(mx, __float_as_int(n1));
    }
}

// ---------------- HMMA bf16 distance pass (occ 2, double-buffered stage) ---
// Per unit (CTA, 256 thr = 8 warps in 2m x 4n): 64 rows x 1024 codes, D=512.
// Z resident in SMEM (64 x 512 bf16, row stride 1040B = 16B skew).
// Codebook streamed in 128 x 64 chunks (row stride 144B), TWO stage buffers,
// ONE __syncthreads per chunk. cn read via __ldg in epilogue (L2-resident).
#define SM2_Z      0
#define SM2_C      66560
#define SM2_STAGE  18432
#define SM2_TOTAL  (SM2_C + 2 * SM2_STAGE)    // 103424
#define SM2_SV     SM2_Z
#define SM2_SK     (SM2_Z + 8192)

__global__ __launch_bounds__(256, 2) void dist_hmma_kernel(
    const __nv_bfloat16* __restrict__ zbfA, const __nv_bfloat16* __restrict__ cbfA,
    const float* __restrict__ cnA,
    const __nv_bfloat16* __restrict__ zbfB, const __nv_bfloat16* __restrict__ cbfB,
    const float* __restrict__ cnB,
    float* __restrict__ cvout, int* __restrict__ ckout)
{
    extern __shared__ __align__(16) char smem[];
    char* sZ = smem + SM2_Z;
    const uint32_t sbase = smem_u32(smem);

    const int tid = threadIdx.x, wid = tid >> 5, lane = tid & 31;
    const int u = blockIdx.x;

    const __nv_bfloat16 *zsrc, *csrc;
    const float* cn;
    int rowBase, kBase;
    if (u < 512) {
        zsrc = zbfA; csrc = cbfA; cn = cnA; rowBase = u * 64; kBase = 0;
    } else {
        int v = u - 512;
        zsrc = zbfB; csrc = cbfB; cn = cnB;
        rowBase = (v >> 2) * 64; kBase = (v & 3) * 1024;
    }

    // load Z tile: 64 rows x 512 bf16
#pragma unroll
    for (int i = 0; i < 16; i++) {
        int c = tid + 256 * i;       // 16B chunk id, 0..4095
        int r = c >> 6, c8 = c & 63;
        uint4 v = *(const uint4*)(zsrc + (((size_t)(rowBase + r)) << 9) + c8 * 8);
        *(uint4*)(sZ + r * 1040 + c8 * 16) = v;
    }

    const int wm = wid >> 2, wn = wid & 3;
    const uint32_t zaddr0 = sbase + SM2_Z +
        (uint32_t)((wm * 32 + (lane & 15)) * 1040 + (lane >> 4) * 16);
    const uint32_t coff = (uint32_t)((wn * 32 + ((lane >> 4) << 3) + (lane & 7)) * 144 +
                                     ((lane >> 3) & 1) * 16);

    float tv[4][2]; int tk[4][2];
#pragma unroll
    for (int i = 0; i < 4; i++)
#pragma unroll
        for (int s = 0; s < 2; s++) { tv[i][s] = FLT_MAX; tk[i][s] = 0; }

    float acc[2][4][4];
#pragma unroll
    for (int mt = 0; mt < 2; mt++)
#pragma unroll
        for (int nt = 0; nt < 4; nt++)
#pragma unroll
            for (int q = 0; q < 4; q++) acc[mt][nt][q] = 0.f;

#define LDGC(pf, cc) do { \
        int _t = (cc) >> 3, _dc = (cc) & 7; \
        _Pragma("unroll") \
        for (int _j = 0; _j < 4; _j++) { \
            int _id = tid + 256 * _j; int _r = _id >> 3, _c8 = _id & 7; \
            (pf)[_j] = *(const uint4*)(csrc + (((size_t)(kBase + _t * 128 + _r)) << 9) \
                                       + _dc * 64 + _c8 * 8); \
        } \
    } while (0)
#define STSC(pf, cc) do { \
        char* _sp = smem + SM2_C + ((cc) & 1) * SM2_STAGE; \
        _Pragma("unroll") \
        for (int _j = 0; _j < 4; _j++) { \
            int _id = tid + 256 * _j; int _r = _id >> 3, _c8 = _id & 7; \
            *(uint4*)(_sp + _r * 144 + _c8 * 16) = (pf)[_j]; \
        } \
    } while (0)

    uint4 pf[4];
    // prologue: stage chunk 0, prefetch chunk 1
    LDGC(pf, 0);
    STSC(pf, 0);
    LDGC(pf, 1);
    __syncthreads();   // buf0 visible

    for (int c = 0; c < 64; c++) {
        // stage chunk c+1 into the other buffer (its old occupant, chunk c-1,
        // was fully consumed before the barrier ending iteration c-1)
        if (c + 1 < 64) {
            STSC(pf, c + 1);
            if (c + 2 < 64) LDGC(pf, c + 2);
        }

        // compute chunk c from buf[c&1]
        const int dc = c & 7;
        const uint32_t caddr0 = sbase + (uint32_t)(SM2_C + (c & 1) * SM2_STAGE) + coff;
#pragma unroll
        for (int ks = 0; ks < 4; ks++) {
            uint32_t b[8];
            ldsm4(b[0], b[1], b[2], b[3], caddr0 + ks * 32);
            ldsm4(b[4], b[5], b[6], b[7], caddr0 + 16 * 144 + ks * 32);
            uint32_t a[2][4];
#pragma unroll
            for (int mt = 0; mt < 2; mt++)
                ldsm4(a[mt][0], a[mt][1], a[mt][2], a[mt][3],
                      zaddr0 + (uint32_t)(mt * 16 * 1040 + (dc * 64 + ks * 16) * 2));
#pragma unroll
            for (int mt = 0; mt < 2; mt++)
#pragma unroll
                for (int nt = 0; nt < 4; nt++)
                    mma_bf16(acc[mt][nt], a[mt], b[(nt >> 1) * 4 + (nt & 1) * 2],
                             b[(nt >> 1) * 4 + (nt & 1) * 2 + 1]);
        }

        if (dc == 7) {
            // epilogue: fold tile into per-thread top-2 per row (cn via L2)
            const int kTile = kBase + (c >> 3) * 128;
            float cnv[8];
#pragma unroll
            for (int nt = 0; nt < 4; nt++)
#pragma unroll
                for (int cc2 = 0; cc2 < 2; cc2++)
                    cnv[nt * 2 + cc2] = __ldg(&cn[kTile + wn * 32 + nt * 8 + (lane & 3) * 2 + cc2]);
#pragma unroll
            for (int mt = 0; mt < 2; mt++)
#pragma unroll
                for (int half = 0; half < 2; half++) {
                    int i = mt * 2 + half;
#pragma unroll
                    for (int nt = 0; nt < 4; nt++)
#pragma unroll
                        for (int cc2 = 0; cc2 < 2; cc2++) {
                            int col = wn * 32 + nt * 8 + (lane & 3) * 2 + cc2;
                            float s = acc[mt][nt][half * 2 + cc2];
                            float v = fmaf(-2.f, s, cnv[nt * 2 + cc2]);
                            int k = kTile + col;
                            if (v < tv[i][0]) {
                                tv[i][1] = tv[i][0]; tk[i][1] = tk[i][0];
                                tv[i][0] = v; tk[i][0] = k;
                            } else if (v < tv[i][1]) {
                                tv[i][1] = v; tk[i][1] = k;
                            }
                        }
                }
#pragma unroll
            for (int mt = 0; mt < 2; mt++)
#pragma unroll
                for (int nt = 0; nt < 4; nt++)
#pragma unroll
                    for (int q = 0; q < 4; q++) acc[mt][nt][q] = 0.f;
        }
        __syncthreads();   // chunk c consumed; stage c+1 visible
    }

    // stage candidates in SMEM (reuse Z area), then coalesced store
    float* sv = (float*)(smem + SM2_SV);
    int*   sk = (int*)(smem + SM2_SK);
#pragma unroll
    for (int i = 0; i < 4; i++) {
        int r = wm * 32 + (i >> 1) * 16 + (i & 1) * 8 + (lane >> 2);
        int slot0 = wn * 8 + (lane & 3) * 2;
#pragma unroll
        for (int s = 0; s < 2; s++) {
            sv[r * 32 + slot0 + s] = tv[i][s];
            sk[r * 32 + slot0 + s] = tk[i][s];
        }
    }
    __syncthreads();
#pragma unroll
    for (int j = 0; j < 8; j++) {
        int idx = tid + 256 * j;
        cvout[(size_t)u * 2048 + idx] = sv[idx];
        ckout[(size_t)u * 2048 + idx] = sk[idx];
    }
#undef LDGC
#undef STSC
}

// ---------------- exact fp32 refinement (parallel candidate preload) -------
__global__ __launch_bounds__(256) void refine_kernel(
    const float* __restrict__ zreA, const float* __restrict__ zimA,
    const float* __restrict__ cbA, const float* __restrict__ cnA,
    const float* __restrict__ zreB, const float* __restrict__ zimB,
    const float* __restrict__ cbB, const float* __restrict__ cnB,
    const float* __restrict__ cv, const int* __restrict__ ck,
    const int* __restrict__ maxcn,
    int* __restrict__ idxA, int* __restrict__ idxB)
{
    int wid = threadIdx.x >> 5, lane = threadIdx.x & 31;
    int gw = blockIdx.x * 8 + wid;
    int n = gw >> 1, cbk = gw & 1;
    const float *zre, *zim, *cb, *cn;
    int* idxo;
    int cnt;
    size_t base;
    if (cbk == 0) {
        zre = zreA; zim = zimA; cb = cbA; cn = cnA; idxo = idxA;
        cnt = 32;
        base = (size_t)(n >> 6) * 2048 + (size_t)(n & 63) * 32;
    } else {
        zre = zreB; zim = zimB; cb = cbB; cn = cnB; idxo = idxB;
        cnt = 128;
        base = (size_t)(512 + (n >> 6) * 4) * 2048 + (size_t)(n & 63) * 32;
    }

    float candv[4]; int candk[4];
    const int nj = cnt >> 5;
#pragma unroll
    for (int j = 0; j < 4; j++) {
        if (j < nj) {
            size_t a = base + (size_t)j * 2048 + lane;
            candv[j] = cv[a];
            candk[j] = ck[a];
        } else { candv[j] = FLT_MAX; candk[j] = 0x7fffffff; }
    }

    float zr[16];
    float zn2 = 0.f;
#pragma unroll
    for (int j = 0; j < 16; j++) {
        int d = lane + 32 * j;
        float z = (d < GLD) ? zre[(size_t)n * GLD + d] : zim[(size_t)n * GLD + d - GLD];
        zr[j] = z;
        zn2 = fmaf(z, z, zn2);
    }
#pragma unroll
    for (int o = 16; o; o >>= 1) zn2 += __shfl_xor_sync(0xffffffffu, zn2, o);

    float vb = fminf(fminf(candv[0], candv[1]), fminf(candv[2], candv[3]));
#pragma unroll
    for (int o = 16; o; o >>= 1) vb = fminf(vb, __shfl_xor_sync(0xffffffffu, vb, o));

    float maxc2 = __int_as_float(maxcn[cbk]);
    float vlim = vb + 0.03125f * sqrtf(zn2 * maxc2) + 0.125f;

    float bd = FLT_MAX; int bk = 0x7fffffff;
    for (int i = 0; i < cnt; i++) {
        float v = __shfl_sync(0xffffffffu, candv[i >> 5], i & 31);
        if (v <= vlim) {
            int k = __shfl_sync(0xffffffffu, candk[i >> 5], i & 31);
            const float* crow = cb + (size_t)k * GD;
            float s = 0.f;
#pragma unroll
            for (int j = 0; j < 16; j++) s = fmaf(zr[j], crow[lane + 32 * j], s);
#pragma unroll
            for (int o = 16; o; o >>= 1) s += __shfl_xor_sync(0xffffffffu, s, o);
            float d = fmaf(-2.f, s, cn[k]);
            if (d < bd || (d == bd && k < bk)) { bd = d; bk = k; }
        }
    }
    if (lane == 0) idxo[n] = bk;
}

// ---- fused per-row: counts/pair scatter + esum scatter + zq write + loss ----
__global__ __launch_bounds__(128) void fuse_row_kernel(
    const float* __restrict__ zre, const float* __restrict__ zim,
    const int* __restrict__ idx, const int* __restrict__ prev,
    const float* __restrict__ cb,
    float* __restrict__ counts, float* __restrict__ esum, int* __restrict__ pair, int K,
    float* __restrict__ zq, float* __restrict__ idxf, float* __restrict__ lossPart)
{
    __shared__ float sh[4];
    int n = blockIdx.x, t = threadIdx.x;
    int lane = t & 31, w = t >> 5;
    int i = idx[n];
    if (t == 0) {
        atomicAdd(&counts[i], 1.f);
        atomicAdd(&pair[(size_t)prev[n] * K + i], 1);
        idxf[n] = (float)i;
    }
    int d = t * 4;
    const float* zsrc = (d < GLD) ? zre + (size_t)n * GLD + d
                                  : zim + (size_t)n * GLD + (d - GLD);
    float4 z = *(const float4*)zsrc;
    float4 q = *(const float4*)(cb + (size_t)i * GD + d);
    *(float4*)(zq + (size_t)n * GD + d) = q;
    float dx = q.x - z.x, dy = q.y - z.y, dz = q.z - z.z, dw = q.w - z.w;
    float s = dx * dx + dy * dy + dz * dz + dw * dw;
    red_add_v4(esum + (size_t)i * GD + d, z);
#pragma unroll
    for (int o = 16; o; o >>= 1) s += __shfl_down_sync(0xffffffffu, s, o);
    if (lane == 0) sh[w] = s;
    __syncthreads();
    if (t == 0) atomicAdd(&lossPart[n & 511], sh[0] + sh[1] + sh[2] + sh[3]);
}

// ---------------- cluster_size EMA + n reduction ----------------
__global__ void clnew_kernel(const float* __restrict__ cl, const float* __restrict__ counts,
                             float* __restrict__ clnew, float* __restrict__ nsum, int K)
{
    int k = blockIdx.x * 256 + threadIdx.x;
    float v = 0.f;
    if (k < K) {
        v = cl[k] * 0.99f + 0.01f * counts[k];
        clnew[k] = v;
    }
    v = blk_reduce_256(v);
    if (threadIdx.x == 0) atomicAdd(nsum, v);
}

// ---------------- codebook EMA update ----------------
__global__ void cbnew_kernel(const float* __restrict__ avg, const float* __restrict__ esum,
                             const float* __restrict__ clnew, const float* __restrict__ nsum,
                             float* __restrict__ out, int K)
{
    size_t idx = (size_t)blockIdx.x * 256 + threadIdx.x;
    int k = (int)(idx >> 9);
    float n = *nsum;
    float cs = (clnew[k] + 1e-6f) / (n + (float)K * 1e-6f) * n;
    float a = avg[idx] * 0.99f + 0.01f * esum[idx];
    out[idx] = a / cs;
}

__global__ void finalize_loss_kernel(const float* __restrict__ lacc, float* __restrict__ out) {
    __shared__ float sh[8];
    int t = threadIdx.x, lane = t & 31, w = t >> 5;
    float s = lacc[t] + lacc[t + 256];
#pragma unroll
    for (int o = 16; o; o >>= 1) s += __shfl_down_sync(0xffffffffu, s, o);
    if (lane == 0) sh[w] = s;
    __syncthreads();
    if (t == 0) {
        float v = 0.f;
#pragma unroll
        for (int j = 0; j < 8; j++) v += sh[j];
        out[0] = 1.25f * v / 16777216.f;
    }
}

// ---------------- sparse adjacency update ----------------
__global__ void adj_sparse_kernel(const int* __restrict__ prev, const int* __restrict__ idxv,
                                  int K, int* __restrict__ pair,
                                  const float* __restrict__ adj, float* __restrict__ out)
{
    int n = blockIdx.x * 256 + threadIdx.x;
    size_t p = (size_t)prev[n] * K + idxv[n];
    int c = atomicExch(&pair[p], 0);
    if (c > 0) {
        float pw = __powf(0.99f, (float)c);
        out[p] = fmaf(adj[p], pw, (1.f - pw) * 100.f);
    }
}

// ---------------- launch ----------------
extern "C" void kernel_launch(void* const* d_in, const int* in_sizes, int n_in,
                              void* d_out, int out_size)
{
    const float* zre_f = (const float*)d_in[0];
    const float* zim_f = (const float*)d_in[1];
    const float* zre_s = (const float*)d_in[2];
    const float* zim_s = (const float*)d_in[3];
    const int*   prev_syn = (const int*)d_in[4];
    const int*   prev_sem = (const int*)d_in[5];
    const float* cb_syn = (const float*)d_in[6];
    const float* cb_sem = (const float*)d_in[7];
    const float* cl_syn = (const float*)d_in[8];
    const float* avg_syn = (const float*)d_in[9];
    const float* cl_sem = (const float*)d_in[10];
    const float* avg_sem = (const float*)d_in[11];
    const float* adj_syn = (const float*)d_in[12];
    const float* adj_sem = (const float*)d_in[13];

    float* out = (float*)d_out;
    const size_t OFF_ZQ_SYN = 0;
    const size_t OFF_ZQ_SEM = OFF_ZQ_SYN + (size_t)GN * GD;
    const size_t OFF_LOSS   = OFF_ZQ_SEM + (size_t)GN * GD;
    const size_t OFF_IDX_SYN = OFF_LOSS + 1;
    const size_t OFF_IDX_SEM = OFF_IDX_SYN + GN;
    const size_t OFF_CB_SYN  = OFF_IDX_SEM + GN;
    const size_t OFF_CB_SEM  = OFF_CB_SYN + (size_t)KS * GD;
    const size_t OFF_ADJ_SYN = OFF_CB_SEM + (size_t)KM * GD;
    const size_t OFF_ADJ_SEM = OFF_ADJ_SYN + (size_t)KS * KS;

    void *p_esum_syn, *p_esum_sem, *p_cnt_syn, *p_cnt_sem, *p_pair_syn, *p_pair_sem;
    void *p_idx_syn, *p_idx_sem, *p_cn_syn, *p_cn_sem, *p_cl_syn, *p_cl_sem, *p_nsum, *p_loss;
    void *p_maxcn, *p_zbf_syn, *p_zbf_sem, *p_cbf_syn, *p_cbf_sem, *p_cv, *p_ck;
    cudaGetSymbolAddress(&p_esum_syn, g_esum_syn);
    cudaGetSymbolAddress(&p_esum_sem, g_esum_sem);
    cudaGetSymbolAddress(&p_cnt_syn, g_counts_syn);
    cudaGetSymbolAddress(&p_cnt_sem, g_counts_sem);
    cudaGetSymbolAddress(&p_pair_syn, g_pair_syn);
    cudaGetSymbolAddress(&p_pair_sem, g_pair_sem);
    cudaGetSymbolAddress(&p_idx_syn, g_idx_syn);
    cudaGetSymbolAddress(&p_idx_sem, g_idx_sem);
    cudaGetSymbolAddress(&p_cn_syn, g_cnorm_syn);
    cudaGetSymbolAddress(&p_cn_sem, g_cnorm_sem);
    cudaGetSymbolAddress(&p_cl_syn, g_clnew_syn);
    cudaGetSymbolAddress(&p_cl_sem, g_clnew_sem);
    cudaGetSymbolAddress(&p_nsum, g_nsum);
    cudaGetSymbolAddress(&p_loss, g_losspart);
    cudaGetSymbolAddress(&p_maxcn, g_maxcn);
    cudaGetSymbolAddress(&p_zbf_syn, g_zbf_syn);
    cudaGetSymbolAddress(&p_zbf_sem, g_zbf_sem);
    cudaGetSymbolAddress(&p_cbf_syn, g_cbf_syn);
    cudaGetSymbolAddress(&p_cbf_sem, g_cbf_sem);
    cudaGetSymbolAddress(&p_cv, g_cv);
    cudaGetSymbolAddress(&p_ck, g_ck);

    cudaFuncSetAttribute(dist_hmma_kernel,
                         cudaFuncAttributeMaxDynamicSharedMemorySize, SM2_TOTAL);

    // 1) zero scratch (pair arrays are self-draining via adj_sparse; no memset)
    cudaMemsetAsync(p_esum_syn, 0, (size_t)KS * GD * sizeof(float));
    cudaMemsetAsync(p_esum_sem, 0, (size_t)KM * GD * sizeof(float));
    cudaMemsetAsync(p_cnt_syn, 0, KS * sizeof(float));
    cudaMemsetAsync(p_cnt_sem, 0, KM * sizeof(float));
    cudaMemsetAsync(p_nsum, 0, 2 * sizeof(float));
    cudaMemsetAsync(p_loss, 0, 512 * sizeof(float));
    cudaMemsetAsync(p_maxcn, 0, 2 * sizeof(int));

    // 2) pre-fill adjacency outputs with pass-through values
    cudaMemcpyAsync(out + OFF_ADJ_SYN, adj_syn, (size_t)KS * KS * sizeof(float),
                    cudaMemcpyDeviceToDevice);
    cudaMemcpyAsync(out + OFF_ADJ_SEM, adj_sem, (size_t)KM * KM * sizeof(float),
                    cudaMemcpyDeviceToDevice);

    // 3) conversions (+ fused codebook norms)
    cvt_z_kernel<<<(GN * GD) / 4096, 256>>>(zre_f, zim_f, (__nv_bfloat16*)p_zbf_syn);
    cvt_z_kernel<<<(GN * GD) / 4096, 256>>>(zre_s, zim_s, (__nv_bfloat16*)p_zbf_sem);
    cvt_cb_norm_kernel<<<KS / 2, 256>>>(cb_syn, (__nv_bfloat16*)p_cbf_syn,
                                        (float*)p_cn_syn, (int*)p_maxcn);
    cvt_cb_norm_kernel<<<KM / 2, 256>>>(cb_sem, (__nv_bfloat16*)p_cbf_sem,
                                        (float*)p_cn_sem, ((int*)p_maxcn) + 1);

    // 4) HMMA approximate distance pass (occ 2, double-buffered)
    dist_hmma_kernel<<<NUNITS2, 256, SM2_TOTAL>>>(
        (const __nv_bfloat16*)p_zbf_syn, (const __nv_bfloat16*)p_cbf_syn, (const float*)p_cn_syn,
        (const __nv_bfloat16*)p_zbf_sem, (const __nv_bfloat16*)p_cbf_sem, (const float*)p_cn_sem,
        (float*)p_cv, (int*)p_ck);

    // 5) exact fp32 refinement -> final indices
    refine_kernel<<<(2 * GN) / 8, 256>>>(
        zre_f, zim_f, cb_syn, (const float*)p_cn_syn,
        zre_s, zim_s, cb_sem, (const float*)p_cn_sem,
        (const float*)p_cv, (const int*)p_ck, (const int*)p_maxcn,
        (int*)p_idx_syn, (int*)p_idx_sem);

    // 6) fused per-row scatter + zq + loss (vector red for esum)
    fuse_row_kernel<<<GN, 128>>>(zre_f, zim_f, (const int*)p_idx_syn, prev_syn, cb_syn,
                                 (float*)p_cnt_syn, (float*)p_esum_syn, (int*)p_pair_syn, KS,
                                 out + OFF_ZQ_SYN, out + OFF_IDX_SYN, (float*)p_loss);
    fuse_row_kernel<<<GN, 128>>>(zre_s, zim_s, (const int*)p_idx_sem, prev_sem, cb_sem,
                                 (float*)p_cnt_sem, (float*)p_esum_sem, (int*)p_pair_sem, KM,
                                 out + OFF_ZQ_SEM, out + OFF_IDX_SEM, (float*)p_loss);

    // 7) cluster size EMA + n
    clnew_kernel<<<KS / 256, 256>>>(cl_syn, (const float*)p_cnt_syn,
                                    (float*)p_cl_syn, (float*)p_nsum, KS);
    clnew_kernel<<<KM / 256, 256>>>(cl_sem, (const float*)p_cnt_sem,
                                    (float*)p_cl_sem, ((float*)p_nsum) + 1, KM);

    // 8) codebook EMA update
    cbnew_kernel<<<(KS * GD) / 256, 256>>>(avg_syn, (const float*)p_esum_syn,
                                           (const float*)p_cl_syn, (const float*)p_nsum,
                                           out + OFF_CB_SYN, KS);
    cbnew_kernel<<<(KM * GD) / 256, 256>>>(avg_sem, (const float*)p_esum_sem,
                                           (const float*)p_cl_sem, ((const float*)p_nsum) + 1,
                                           out + OFF_CB_SEM, KM);

    // 9) loss finalize
    finalize_loss_kernel<<<1, 256>>>((const float*)p_loss, out + OFF_LOSS);

    // 10) sparse adjacency updates (drain pair counts)
    adj_sparse_kernel<<<GN / 256, 256>>>(prev_syn, (const int*)p_idx_syn, KS,
                                         (int*)p_pair_syn, adj_syn, out + OFF_ADJ_SYN);
    adj_sparse_kernel<<<GN / 256, 256>>>(prev_sem, (const int*)p_idx_sem, KM,
                                         (int*)p_pair_sem, adj_sem, out + OFF_ADJ_SEM);
    (void)in_sizes; (void)n_in; (void)out_size;
}

// round 16
// speedup vs baseline: 1.2171x; 1.0356x over previous
#include <cuda_runtime.h>
#include <cuda_bf16.h>
#include <math.h>
#include <float.h>
#include <stdint.h>

// Problem constants
#define GN   32768
#define GLD  256
#define GD   512
#define KS   1024
#define KM   4096
// 64-row units: 512 syn + 2048 sem (512 row-tiles x 4 k-chunks)
#define NUNITS2 2560

// ---------------- scratch (static __device__, no allocation) ----------------
static __device__ __align__(16) float g_esum_syn[KS * GD];
static __device__ __align__(16) float g_esum_sem[KM * GD];
static __device__ float g_counts_syn[KS];
static __device__ float g_counts_sem[KM];
static __device__ int   g_pair_syn[(size_t)KS * KS];   // self-draining (adj_sparse)
static __device__ int   g_pair_sem[(size_t)KM * KM];   // self-draining (adj_sparse)
static __device__ int   g_idx_syn[GN];
static __device__ int   g_idx_sem[GN];
static __device__ float g_cnorm_syn[KS];
static __device__ float g_cnorm_sem[KM];
static __device__ float g_clnew_syn[KS];
static __device__ float g_clnew_sem[KM];
static __device__ float g_nsum[2];
static __device__ float g_losspart[512];
static __device__ int   g_maxcn[2];
// bf16 copies (16B-aligned for uint4 access)
static __device__ __align__(16) __nv_bfloat16 g_zbf_syn[(size_t)GN * GD];
static __device__ __align__(16) __nv_bfloat16 g_zbf_sem[(size_t)GN * GD];
static __device__ __align__(16) __nv_bfloat16 g_cbf_syn[(size_t)KS * GD];
static __device__ __align__(16) __nv_bfloat16 g_cbf_sem[(size_t)KM * GD];
// candidates: per (unit): 64 rows x 32 slots = 2048 entries
static __device__ float g_cv[(size_t)NUNITS2 * 2048];
static __device__ int   g_ck[(size_t)NUNITS2 * 2048];

// ---------------- PTX helpers (arch-agnostic: ldmatrix + mma.sync) ----------
__device__ __forceinline__ uint32_t smem_u32(const void* p) {
    uint32_t a;
    asm("{ .reg .u64 t; cvta.to.shared.u64 t, %1; cvt.u32.u64 %0, t; }" : "=r"(a) : "l"(p));
    return a;
}
__device__ __forceinline__ void ldsm4(uint32_t& r0, uint32_t& r1, uint32_t& r2, uint32_t& r3,
                                      uint32_t addr) {
    asm volatile("ldmatrix.sync.aligned.m8n8.x4.shared.b16 {%0,%1,%2,%3}, [%4];"
                 : "=r"(r0), "=r"(r1), "=r"(r2), "=r"(r3) : "r"(addr));
}
__device__ __forceinline__ void mma_bf16(float* d, const uint32_t* a, uint32_t b0, uint32_t b1) {
    asm volatile("mma.sync.aligned.m16n8k16.row.col.f32.bf16.bf16.f32 "
                 "{%0,%1,%2,%3}, {%4,%5,%6,%7}, {%8,%9}, {%0,%1,%2,%3};"
                 : "+f"(d[0]), "+f"(d[1]), "+f"(d[2]), "+f"(d[3])
                 : "r"(a[0]), "r"(a[1]), "r"(a[2]), "r"(a[3]), "r"(b0), "r"(b1));
}
__device__ __forceinline__ void red_add_v4(float* gptr, float4 v) {
    asm volatile("red.global.add.v4.f32 [%0], {%1, %2, %3, %4};"
                 :: "l"(gptr), "f"(v.x), "f"(v.y), "f"(v.z), "f"(v.w) : "memory");
}

// ---------------- generic helpers ----------------
__device__ __forceinline__ float blk_reduce_256(float v) {
    __shared__ float sh[8];
    int lane = threadIdx.x & 31, w = threadIdx.x >> 5;
#pragma unroll
    for (int o = 16; o; o >>= 1) v += __shfl_down_sync(0xffffffffu, v, o);
    if (lane == 0) sh[w] = v;
    __syncthreads();
    if (w == 0) {
        v = (lane < 8) ? sh[lane] : 0.f;
#pragma unroll
        for (int o = 4; o; o >>= 1) v += __shfl_down_sync(0xffffffffu, v, o);
    }
    return v;
}

// ---------------- conversions ----------------
// both codebooks in one launch; 8 float4 groups per thread (MLP=8).
// grid = 2 * GN*GD/8192; blocks [0,2048) syn, [2048,4096) sem.
__global__ void cvt_z_all_kernel(const float* __restrict__ reA, const float* __restrict__ imA,
                                 __nv_bfloat16* __restrict__ outA,
                                 const float* __restrict__ reB, const float* __restrict__ imB,
                                 __nv_bfloat16* __restrict__ outB) {
    int b = blockIdx.x;
    const float *re, *im;
    __nv_bfloat16* out;
    if (b < 2048) { re = reA; im = imA; out = outA; }
    else          { re = reB; im = imB; out = outB; b -= 2048; }
#pragma unroll
    for (int j = 0; j < 8; j++) {
        size_t e = (size_t)b * 8192 + j * 1024 + threadIdx.x * 4;
        int n = (int)(e >> 9), d = (int)(e & 511);
        const float* s = (d < GLD) ? re + (size_t)n * GLD + d
                                   : im + (size_t)n * GLD + (d - GLD);
        float4 v = *(const float4*)s;
        __nv_bfloat162 a = __floats2bfloat162_rn(v.x, v.y);
        __nv_bfloat162 c = __floats2bfloat162_rn(v.z, v.w);
        ((__nv_bfloat162*)(out + e))[0] = a;
        ((__nv_bfloat162*)(out + e))[1] = c;
    }
}

// fused codebook convert + per-row squared norms + max
__global__ void cvt_cb_norm_kernel(const float* __restrict__ cb, __nv_bfloat16* __restrict__ out,
                                   float* __restrict__ norms, int* __restrict__ mx) {
    __shared__ float sh[8];
    int t = threadIdx.x, lane = t & 31, w = t >> 5;
    size_t e = ((size_t)blockIdx.x * 256 + t) * 4;
    float4 v = *(const float4*)(cb + e);
    __nv_bfloat162 a = __floats2bfloat162_rn(v.x, v.y);
    __nv_bfloat162 b = __floats2bfloat162_rn(v.z, v.w);
    ((__nv_bfloat162*)(out + e))[0] = a;
    ((__nv_bfloat162*)(out + e))[1] = b;
    float s = v.x * v.x + v.y * v.y + v.z * v.z + v.w * v.w;
#pragma unroll
    for (int o = 16; o; o >>= 1) s += __shfl_xor_sync(0xffffffffu, s, o);
    if (lane == 0) sh[w] = s;
    __syncthreads();
    if (t == 0) {
        float n0 = sh[0] + sh[1] + sh[2] + sh[3];
        norms[blockIdx.x * 2] = n0;
        atomicMax(mx, __float_as_int(n0));
    } else if (t == 128) {
        float n1 = sh[4] + sh[5] + sh[6] + sh[7];
        norms[blockIdx.x * 2 + 1] = n1;
        atomicMax(mx, __float_as_int(n1));
    }
}

// ---------------- HMMA bf16 distance pass (FROZEN: at HMMA issue floor) ----
#define SM2_Z      0
#define SM2_C      66560
#define SM2_STAGE  18432
#define SM2_TOTAL  (SM2_C + 2 * SM2_STAGE)    // 103424
#define SM2_SV     SM2_Z
#define SM2_SK     (SM2_Z + 8192)

__global__ __launch_bounds__(256, 2) void dist_hmma_kernel(
    const __nv_bfloat16* __restrict__ zbfA, const __nv_bfloat16* __restrict__ cbfA,
    const float* __restrict__ cnA,
    const __nv_bfloat16* __restrict__ zbfB, const __nv_bfloat16* __restrict__ cbfB,
    const float* __restrict__ cnB,
    float* __restrict__ cvout, int* __restrict__ ckout)
{
    extern __shared__ __align__(16) char smem[];
    char* sZ = smem + SM2_Z;
    const uint32_t sbase = smem_u32(smem);

    const int tid = threadIdx.x, wid = tid >> 5, lane = tid & 31;
    const int u = blockIdx.x;

    const __nv_bfloat16 *zsrc, *csrc;
    const float* cn;
    int rowBase, kBase;
    if (u < 512) {
        zsrc = zbfA; csrc = cbfA; cn = cnA; rowBase = u * 64; kBase = 0;
    } else {
        int v = u - 512;
        zsrc = zbfB; csrc = cbfB; cn = cnB;
        rowBase = (v >> 2) * 64; kBase = (v & 3) * 1024;
    }

#pragma unroll
    for (int i = 0; i < 16; i++) {
        int c = tid + 256 * i;
        int r = c >> 6, c8 = c & 63;
        uint4 v = *(const uint4*)(zsrc + (((size_t)(rowBase + r)) << 9) + c8 * 8);
        *(uint4*)(sZ + r * 1040 + c8 * 16) = v;
    }

    const int wm = wid >> 2, wn = wid & 3;
    const uint32_t zaddr0 = sbase + SM2_Z +
        (uint32_t)((wm * 32 + (lane & 15)) * 1040 + (lane >> 4) * 16);
    const uint32_t coff = (uint32_t)((wn * 32 + ((lane >> 4) << 3) + (lane & 7)) * 144 +
                                     ((lane >> 3) & 1) * 16);

    float tv[4][2]; int tk[4][2];
#pragma unroll
    for (int i = 0; i < 4; i++)
#pragma unroll
        for (int s = 0; s < 2; s++) { tv[i][s] = FLT_MAX; tk[i][s] = 0; }

    float acc[2][4][4];
#pragma unroll
    for (int mt = 0; mt < 2; mt++)
#pragma unroll
        for (int nt = 0; nt < 4; nt++)
#pragma unroll
            for (int q = 0; q < 4; q++) acc[mt][nt][q] = 0.f;

#define LDGC(pf, cc) do { \
        int _t = (cc) >> 3, _dc = (cc) & 7; \
        _Pragma("unroll") \
        for (int _j = 0; _j < 4; _j++) { \
            int _id = tid + 256 * _j; int _r = _id >> 3, _c8 = _id & 7; \
            (pf)[_j] = *(const uint4*)(csrc + (((size_t)(kBase + _t * 128 + _r)) << 9) \
                                       + _dc * 64 + _c8 * 8); \
        } \
    } while (0)
#define STSC(pf, cc) do { \
        char* _sp = smem + SM2_C + ((cc) & 1) * SM2_STAGE; \
        _Pragma("unroll") \
        for (int _j = 0; _j < 4; _j++) { \
            int _id = tid + 256 * _j; int _r = _id >> 3, _c8 = _id & 7; \
            *(uint4*)(_sp + _r * 144 + _c8 * 16) = (pf)[_j]; \
        } \
    } while (0)

    uint4 pf[4];
    LDGC(pf, 0);
    STSC(pf, 0);
    LDGC(pf, 1);
    __syncthreads();

    for (int c = 0; c < 64; c++) {
        if (c + 1 < 64) {
            STSC(pf, c + 1);
            if (c + 2 < 64) LDGC(pf, c + 2);
        }

        const int dc = c & 7;
        const uint32_t caddr0 = sbase + (uint32_t)(SM2_C + (c & 1) * SM2_STAGE) + coff;
#pragma unroll
        for (int ks = 0; ks < 4; ks++) {
            uint32_t b[8];
            ldsm4(b[0], b[1], b[2], b[3], caddr0 + ks * 32);
            ldsm4(b[4], b[5], b[6], b[7], caddr0 + 16 * 144 + ks * 32);
            uint32_t a[2][4];
#pragma unroll
            for (int mt = 0; mt < 2; mt++)
                ldsm4(a[mt][0], a[mt][1], a[mt][2], a[mt][3],
                      zaddr0 + (uint32_t)(mt * 16 * 1040 + (dc * 64 + ks * 16) * 2));
#pragma unroll
            for (int mt = 0; mt < 2; mt++)
#pragma unroll
                for (int nt = 0; nt < 4; nt++)
                    mma_bf16(acc[mt][nt], a[mt], b[(nt >> 1) * 4 + (nt & 1) * 2],
                             b[(nt >> 1) * 4 + (nt & 1) * 2 + 1]);
        }

        if (dc == 7) {
            const int kTile = kBase + (c >> 3) * 128;
            float cnv[8];
#pragma unroll
            for (int nt = 0; nt < 4; nt++)
#pragma unroll
                for (int cc2 = 0; cc2 < 2; cc2++)
                    cnv[nt * 2 + cc2] = __ldg(&cn[kTile + wn * 32 + nt * 8 + (lane & 3) * 2 + cc2]);
#pragma unroll
            for (int mt = 0; mt < 2; mt++)
#pragma unroll
                for (int half = 0; half < 2; half++) {
                    int i = mt * 2 + half;
#pragma unroll
                    for (int nt = 0; nt < 4; nt++)
#pragma unroll
                        for (int cc2 = 0; cc2 < 2; cc2++) {
                            int col = wn * 32 + nt * 8 + (lane & 3) * 2 + cc2;
                            float s = acc[mt][nt][half * 2 + cc2];
                            float v = fmaf(-2.f, s, cnv[nt * 2 + cc2]);
                            int k = kTile + col;
                            if (v < tv[i][0]) {
                                tv[i][1] = tv[i][0]; tk[i][1] = tk[i][0];
                                tv[i][0] = v; tk[i][0] = k;
                            } else if (v < tv[i][1]) {
                                tv[i][1] = v; tk[i][1] = k;
                            }
                        }
                }
#pragma unroll
            for (int mt = 0; mt < 2; mt++)
#pragma unroll
                for (int nt = 0; nt < 4; nt++)
#pragma unroll
                    for (int q = 0; q < 4; q++) acc[mt][nt][q] = 0.f;
        }
        __syncthreads();
    }

    float* sv = (float*)(smem + SM2_SV);
    int*   sk = (int*)(smem + SM2_SK);
#pragma unroll
    for (int i = 0; i < 4; i++) {
        int r = wm * 32 + (i >> 1) * 16 + (i & 1) * 8 + (lane >> 2);
        int slot0 = wn * 8 + (lane & 3) * 2;
#pragma unroll
        for (int s = 0; s < 2; s++) {
            sv[r * 32 + slot0 + s] = tv[i][s];
            sk[r * 32 + slot0 + s] = tk[i][s];
        }
    }
    __syncthreads();
#pragma unroll
    for (int j = 0; j < 8; j++) {
        int idx = tid + 256 * j;
        cvout[(size_t)u * 2048 + idx] = sv[idx];
        ckout[(size_t)u * 2048 + idx] = sk[idx];
    }
#undef LDGC
#undef STSC
}

// ------- fused: exact refinement + scatter + zq write + loss (warp/row) ----
__global__ __launch_bounds__(256) void refine_fuse_kernel(
    const float* __restrict__ zreA, const float* __restrict__ zimA,
    const float* __restrict__ cbA, const float* __restrict__ cnA,
    const float* __restrict__ zreB, const float* __restrict__ zimB,
    const float* __restrict__ cbB, const float* __restrict__ cnB,
    const float* __restrict__ cv, const int* __restrict__ ck,
    const int* __restrict__ maxcn,
    const int* __restrict__ prevA, const int* __restrict__ prevB,
    int* __restrict__ idxA, int* __restrict__ idxB,
    float* __restrict__ cntA, float* __restrict__ cntB,
    float* __restrict__ esA, float* __restrict__ esB,
    int* __restrict__ pairA, int* __restrict__ pairB,
    float* __restrict__ zqA, float* __restrict__ zqB,
    float* __restrict__ idxfA, float* __restrict__ idxfB,
    float* __restrict__ lossPart)
{
    int wid = threadIdx.x >> 5, lane = threadIdx.x & 31;
    int gw = blockIdx.x * 8 + wid;
    int n = gw >> 1, cbk = gw & 1;
    const float *zre, *zim, *cb, *cn;
    const int* prev;
    int* idxo;
    float *cnts, *esum, *zq, *idxf;
    int* pair;
    int cnt, K;
    size_t base;
    if (cbk == 0) {
        zre = zreA; zim = zimA; cb = cbA; cn = cnA; prev = prevA; idxo = idxA;
        cnts = cntA; esum = esA; pair = pairA; zq = zqA; idxf = idxfA;
        cnt = 32; K = KS;
        base = (size_t)(n >> 6) * 2048 + (size_t)(n & 63) * 32;
    } else {
        zre = zreB; zim = zimB; cb = cbB; cn = cnB; prev = prevB; idxo = idxB;
        cnts = cntB; esum = esB; pair = pairB; zq = zqB; idxf = idxfB;
        cnt = 128; K = KM;
        base = (size_t)(512 + (n >> 6) * 4) * 2048 + (size_t)(n & 63) * 32;
    }

    // parallel candidate preload
    float candv[4]; int candk[4];
    const int nj = cnt >> 5;
#pragma unroll
    for (int j = 0; j < 4; j++) {
        if (j < nj) {
            size_t a = base + (size_t)j * 2048 + lane;
            candv[j] = cv[a];
            candk[j] = ck[a];
        } else { candv[j] = FLT_MAX; candk[j] = 0x7fffffff; }
    }

    float zr[16];
    float zn2 = 0.f;
#pragma unroll
    for (int j = 0; j < 16; j++) {
        int d = lane + 32 * j;
        float z = (d < GLD) ? zre[(size_t)n * GLD + d] : zim[(size_t)n * GLD + d - GLD];
        zr[j] = z;
        zn2 = fmaf(z, z, zn2);
    }
#pragma unroll
    for (int o = 16; o; o >>= 1) zn2 += __shfl_xor_sync(0xffffffffu, zn2, o);

    float vb = fminf(fminf(candv[0], candv[1]), fminf(candv[2], candv[3]));
#pragma unroll
    for (int o = 16; o; o >>= 1) vb = fminf(vb, __shfl_xor_sync(0xffffffffu, vb, o));

    float maxc2 = __int_as_float(maxcn[cbk]);
    float vlim = vb + 0.03125f * sqrtf(zn2 * maxc2) + 0.125f;

    float bd = FLT_MAX; int bk = 0x7fffffff;
    for (int i = 0; i < cnt; i++) {
        float v = __shfl_sync(0xffffffffu, candv[i >> 5], i & 31);
        if (v <= vlim) {
            int k = __shfl_sync(0xffffffffu, candk[i >> 5], i & 31);
            const float* crow = cb + (size_t)k * GD;
            float s = 0.f;
#pragma unroll
            for (int j = 0; j < 16; j++) s = fmaf(zr[j], crow[lane + 32 * j], s);
#pragma unroll
            for (int o = 16; o; o >>= 1) s += __shfl_xor_sync(0xffffffffu, s, o);
            float d = fmaf(-2.f, s, cn[k]);
            if (d < bd || (d == bd && k < bk)) { bd = d; bk = k; }
        }
    }

    // phase 2: outputs for winner bk (winner row + z lines are cache-hot)
    if (lane == 0) {
        idxo[n] = bk;
        idxf[n] = (float)bk;
        atomicAdd(&cnts[bk], 1.f);
        atomicAdd(&pair[(size_t)prev[n] * K + bk], 1);
    }
    const float* crow = cb + (size_t)bk * GD;
    float s = 0.f;
#pragma unroll
    for (int j = 0; j < 4; j++) {
        int d = lane * 4 + 128 * j;
        float4 q = *(const float4*)(crow + d);
        const float* zs = (d < GLD) ? zre + (size_t)n * GLD + d
                                    : zim + (size_t)n * GLD + (d - GLD);
        float4 z = *(const float4*)zs;
        *(float4*)(zq + (size_t)n * GD + d) = q;
        float dx = q.x - z.x, dy = q.y - z.y, dz = q.z - z.z, dw = q.w - z.w;
        s += dx * dx + dy * dy + dz * dz + dw * dw;
        red_add_v4(esum + (size_t)bk * GD + d, z);
    }
#pragma unroll
    for (int o = 16; o; o >>= 1) s += __shfl_down_sync(0xffffffffu, s, o);
    if (lane == 0) atomicAdd(&lossPart[n & 511], s);
}

// ---------------- cluster_size EMA + n reduction (both codebooks) ----------
// grid = (KS + KM) / 256 = 20; blocks [0,4) syn, [4,20) sem.
__global__ void clnew_all_kernel(const float* __restrict__ clA, const float* __restrict__ cntA,
                                 float* __restrict__ clnewA,
                                 const float* __restrict__ clB, const float* __restrict__ cntB,
                                 float* __restrict__ clnewB,
                                 float* __restrict__ nsum)
{
    int b = blockIdx.x;
    const float *cl, *cnts;
    float* clnew;
    float* ns;
    int k;
    if (b < 4) { cl = clA; cnts = cntA; clnew = clnewA; ns = nsum;     k = b * 256 + threadIdx.x; }
    else       { cl = clB; cnts = cntB; clnew = clnewB; ns = nsum + 1; k = (b - 4) * 256 + threadIdx.x; }
    float v = cl[k] * 0.99f + 0.01f * cnts[k];
    clnew[k] = v;
    v = blk_reduce_256(v);
    if (threadIdx.x == 0) atomicAdd(ns, v);
}

// ---------------- codebook EMA update (both, float4 loads, scalar stores) --
// grid = (KS+KM)*GD/1024 = 2560; each thread handles 4 elements.
__global__ void cbnew_all_kernel(const float* __restrict__ avgA, const float* __restrict__ esA,
                                 const float* __restrict__ clA, float* __restrict__ outA,
                                 const float* __restrict__ avgB, const float* __restrict__ esB,
                                 const float* __restrict__ clB, float* __restrict__ outB,
                                 const float* __restrict__ nsum)
{
    size_t e4 = ((size_t)blockIdx.x * 256 + threadIdx.x) * 4;
    const float *avg, *es, *cl;
    float* out;
    float n;
    size_t e;
    int K;
    if (e4 < (size_t)KS * GD) {
        avg = avgA; es = esA; cl = clA; out = outA; n = nsum[0]; e = e4; K = KS;
    } else {
        avg = avgB; es = esB; cl = clB; out = outB; n = nsum[1]; e = e4 - (size_t)KS * GD; K = KM;
    }
    int k = (int)(e >> 9);
    float cs = (cl[k] + 1e-6f) / (n + (float)K * 1e-6f) * n;
    float inv = 1.f / cs;
    float4 a = *(const float4*)(avg + e);
    float4 s = *(const float4*)(es + e);
    out[e + 0] = fmaf(a.x, 0.99f, 0.01f * s.x) * inv;
    out[e + 1] = fmaf(a.y, 0.99f, 0.01f * s.y) * inv;
    out[e + 2] = fmaf(a.z, 0.99f, 0.01f * s.z) * inv;
    out[e + 3] = fmaf(a.w, 0.99f, 0.01f * s.w) * inv;
}

__global__ void finalize_loss_kernel(const float* __restrict__ lacc, float* __restrict__ out) {
    __shared__ float sh[8];
    int t = threadIdx.x, lane = t & 31, w = t >> 5;
    float s = lacc[t] + lacc[t + 256];
#pragma unroll
    for (int o = 16; o; o >>= 1) s += __shfl_down_sync(0xffffffffu, s, o);
    if (lane == 0) sh[w] = s;
    __syncthreads();
    if (t == 0) {
        float v = 0.f;
#pragma unroll
        for (int j = 0; j < 8; j++) v += sh[j];
        out[0] = 1.25f * v / 16777216.f;
    }
}

// ---------------- sparse adjacency update (both codebooks) ----------------
// grid = 2*GN/256 = 256; blocks [0,128) syn, [128,256) sem.
__global__ void adj_sparse_all_kernel(
    const int* __restrict__ prevA, const int* __restrict__ idxA, int* __restrict__ pairA,
    const float* __restrict__ adjA, float* __restrict__ outA,
    const int* __restrict__ prevB, const int* __restrict__ idxB, int* __restrict__ pairB,
    const float* __restrict__ adjB, float* __restrict__ outB)
{
    int b = blockIdx.x;
    const int *prev, *idxv;
    int* pair;
    const float* adj;
    float* out;
    int K, n;
    if (b < 128) { prev = prevA; idxv = idxA; pair = pairA; adj = adjA; out = outA; K = KS; n = b * 256 + threadIdx.x; }
    else         { prev = prevB; idxv = idxB; pair = pairB; adj = adjB; out = outB; K = KM; n = (b - 128) * 256 + threadIdx.x; }
    size_t p = (size_t)prev[n] * K + idxv[n];
    int c = atomicExch(&pair[p], 0);
    if (c > 0) {
        float pw = __powf(0.99f, (float)c);
        out[p] = fmaf(adj[p], pw, (1.f - pw) * 100.f);
    }
}

// ---------------- launch ----------------
extern "C" void kernel_launch(void* const* d_in, const int* in_sizes, int n_in,
                              void* d_out, int out_size)
{
    const float* zre_f = (const float*)d_in[0];
    const float* zim_f = (const float*)d_in[1];
    const float* zre_s = (const float*)d_in[2];
    const float* zim_s = (const float*)d_in[3];
    const int*   prev_syn = (const int*)d_in[4];
    const int*   prev_sem = (const int*)d_in[5];
    const float* cb_syn = (const float*)d_in[6];
    const float* cb_sem = (const float*)d_in[7];
    const float* cl_syn = (const float*)d_in[8];
    const float* avg_syn = (const float*)d_in[9];
    const float* cl_sem = (const float*)d_in[10];
    const float* avg_sem = (const float*)d_in[11];
    const float* adj_syn = (const float*)d_in[12];
    const float* adj_sem = (const float*)d_in[13];

    float* out = (float*)d_out;
    const size_t OFF_ZQ_SYN = 0;
    const size_t OFF_ZQ_SEM = OFF_ZQ_SYN + (size_t)GN * GD;
    const size_t OFF_LOSS   = OFF_ZQ_SEM + (size_t)GN * GD;
    const size_t OFF_IDX_SYN = OFF_LOSS + 1;
    const size_t OFF_IDX_SEM = OFF_IDX_SYN + GN;
    const size_t OFF_CB_SYN  = OFF_IDX_SEM + GN;
    const size_t OFF_CB_SEM  = OFF_CB_SYN + (size_t)KS * GD;
    const size_t OFF_ADJ_SYN = OFF_CB_SEM + (size_t)KM * GD;
    const size_t OFF_ADJ_SEM = OFF_ADJ_SYN + (size_t)KS * KS;

    void *p_esum_syn, *p_esum_sem, *p_cnt_syn, *p_cnt_sem, *p_pair_syn, *p_pair_sem;
    void *p_idx_syn, *p_idx_sem, *p_cn_syn, *p_cn_sem, *p_cl_syn, *p_cl_sem, *p_nsum, *p_loss;
    void *p_maxcn, *p_zbf_syn, *p_zbf_sem, *p_cbf_syn, *p_cbf_sem, *p_cv, *p_ck;
    cudaGetSymbolAddress(&p_esum_syn, g_esum_syn);
    cudaGetSymbolAddress(&p_esum_sem, g_esum_sem);
    cudaGetSymbolAddress(&p_cnt_syn, g_counts_syn);
    cudaGetSymbolAddress(&p_cnt_sem, g_counts_sem);
    cudaGetSymbolAddress(&p_pair_syn, g_pair_syn);
    cudaGetSymbolAddress(&p_pair_sem, g_pair_sem);
    cudaGetSymbolAddress(&p_idx_syn, g_idx_syn);
    cudaGetSymbolAddress(&p_idx_sem, g_idx_sem);
    cudaGetSymbolAddress(&p_cn_syn, g_cnorm_syn);
    cudaGetSymbolAddress(&p_cn_sem, g_cnorm_sem);
    cudaGetSymbolAddress(&p_cl_syn, g_clnew_syn);
    cudaGetSymbolAddress(&p_cl_sem, g_clnew_sem);
    cudaGetSymbolAddress(&p_nsum, g_nsum);
    cudaGetSymbolAddress(&p_loss, g_losspart);
    cudaGetSymbolAddress(&p_maxcn, g_maxcn);
    cudaGetSymbolAddress(&p_zbf_syn, g_zbf_syn);
    cudaGetSymbolAddress(&p_zbf_sem, g_zbf_sem);
    cudaGetSymbolAddress(&p_cbf_syn, g_cbf_syn);
    cudaGetSymbolAddress(&p_cbf_sem, g_cbf_sem);
    cudaGetSymbolAddress(&p_cv, g_cv);
    cudaGetSymbolAddress(&p_ck, g_ck);

    cudaFuncSetAttribute(dist_hmma_kernel,
                         cudaFuncAttributeMaxDynamicSharedMemorySize, SM2_TOTAL);

    // 1) zero scratch (pair arrays self-draining)
    cudaMemsetAsync(p_esum_syn, 0, (size_t)KS * GD * sizeof(float));
    cudaMemsetAsync(p_esum_sem, 0, (size_t)KM * GD * sizeof(float));
    cudaMemsetAsync(p_cnt_syn, 0, KS * sizeof(float));
    cudaMemsetAsync(p_cnt_sem, 0, KM * sizeof(float));
    cudaMemsetAsync(p_nsum, 0, 2 * sizeof(float));
    cudaMemsetAsync(p_loss, 0, 512 * sizeof(float));
    cudaMemsetAsync(p_maxcn, 0, 2 * sizeof(int));

    // 2) pre-fill adjacency outputs with pass-through values
    cudaMemcpyAsync(out + OFF_ADJ_SYN, adj_syn, (size_t)KS * KS * sizeof(float),
                    cudaMemcpyDeviceToDevice);
    cudaMemcpyAsync(out + OFF_ADJ_SEM, adj_sem, (size_t)KM * KM * sizeof(float),
                    cudaMemcpyDeviceToDevice);

    // 3) conversions
    cvt_z_all_kernel<<<4096, 256>>>(zre_f, zim_f, (__nv_bfloat16*)p_zbf_syn,
                                    zre_s, zim_s, (__nv_bfloat16*)p_zbf_sem);
    cvt_cb_norm_kernel<<<KS / 2, 256>>>(cb_syn, (__nv_bfloat16*)p_cbf_syn,
                                        (float*)p_cn_syn, (int*)p_maxcn);
    cvt_cb_norm_kernel<<<KM / 2, 256>>>(cb_sem, (__nv_bfloat16*)p_cbf_sem,
                                        (float*)p_cn_sem, ((int*)p_maxcn) + 1);

    // 4) HMMA approximate distance pass (frozen)
    dist_hmma_kernel<<<NUNITS2, 256, SM2_TOTAL>>>(
        (const __nv_bfloat16*)p_zbf_syn, (const __nv_bfloat16*)p_cbf_syn, (const float*)p_cn_syn,
        (const __nv_bfloat16*)p_zbf_sem, (const __nv_bfloat16*)p_cbf_sem, (const float*)p_cn_sem,
        (float*)p_cv, (int*)p_ck);

    // 5) fused refine + scatter + zq + loss
    refine_fuse_kernel<<<(2 * GN) / 8, 256>>>(
        zre_f, zim_f, cb_syn, (const float*)p_cn_syn,
        zre_s, zim_s, cb_sem, (const float*)p_cn_sem,
        (const float*)p_cv, (const int*)p_ck, (const int*)p_maxcn,
        prev_syn, prev_sem,
        (int*)p_idx_syn, (int*)p_idx_sem,
        (float*)p_cnt_syn, (float*)p_cnt_sem,
        (float*)p_esum_syn, (float*)p_esum_sem,
        (int*)p_pair_syn, (int*)p_pair_sem,
        out + OFF_ZQ_SYN, out + OFF_ZQ_SEM,
        out + OFF_IDX_SYN, out + OFF_IDX_SEM,
        (float*)p_loss);

    // 6) cluster size EMA + n (both)
    clnew_all_kernel<<<(KS + KM) / 256, 256>>>(
        cl_syn, (const float*)p_cnt_syn, (float*)p_cl_syn,
        cl_sem, (const float*)p_cnt_sem, (float*)p_cl_sem,
        (float*)p_nsum);

    // 7) codebook EMA update (both)
    cbnew_all_kernel<<<((KS + KM) * GD) / 1024, 256>>>(
        avg_syn, (const float*)p_esum_syn, (const float*)p_cl_syn, out + OFF_CB_SYN,
        avg_sem, (const float*)p_esum_sem, (const float*)p_cl_sem, out + OFF_CB_SEM,
        (const float*)p_nsum);

    // 8) loss finalize
    finalize_loss_kernel<<<1, 256>>>((const float*)p_loss, out + OFF_LOSS);

    // 9) sparse adjacency updates (both; drains pair counts)
    adj_sparse_all_kernel<<<(2 * GN) / 256, 256>>>(
        prev_syn, (const int*)p_idx_syn, (int*)p_pair_syn, adj_syn, out + OFF_ADJ_SYN,
        prev_sem, (const int*)p_idx_sem, (int*)p_pair_sem, adj_sem, out + OFF_ADJ_SEM);
    (void)in_sizes; (void)n_in; (void)out_size;
}

// round 17
// speedup vs baseline: 1.2261x; 1.0073x over previous
#include <cuda_runtime.h>
#include <cuda_bf16.h>
#include <math.h>
#include <float.h>
#include <stdint.h>

// Problem constants
#define GN   32768
#define GLD  256
#define GD   512
#define KS   1024
#define KM   4096
// 64-row units: 512 syn + 2048 sem (512 row-tiles x 4 k-chunks)
#define NUNITS2 2560

// ---------------- scratch (static __device__, no allocation) ----------------
static __device__ __align__(16) float g_esum_syn[KS * GD];
static __device__ __align__(16) float g_esum_sem[KM * GD];
static __device__ float g_counts_syn[KS];
static __device__ float g_counts_sem[KM];
static __device__ int   g_pair_syn[(size_t)KS * KS];   // self-draining (adj_sparse)
static __device__ int   g_pair_sem[(size_t)KM * KM];   // self-draining (adj_sparse)
static __device__ int   g_idx_syn[GN];
static __device__ int   g_idx_sem[GN];
static __device__ float g_cnorm_syn[KS];
static __device__ float g_cnorm_sem[KM];
static __device__ float g_clnew_syn[KS];
static __device__ float g_clnew_sem[KM];
static __device__ float g_nsum[2];
static __device__ float g_losspart[512];
static __device__ int   g_maxcn[2];
// bf16 codebook copies (16B-aligned for uint4 access)
static __device__ __align__(16) __nv_bfloat16 g_cbf_syn[(size_t)KS * GD];
static __device__ __align__(16) __nv_bfloat16 g_cbf_sem[(size_t)KM * GD];
// candidates: per (unit): 64 rows x 32 slots = 2048 entries
static __device__ float g_cv[(size_t)NUNITS2 * 2048];
static __device__ int   g_ck[(size_t)NUNITS2 * 2048];

// ---------------- PTX helpers (arch-agnostic: ldmatrix + mma.sync) ----------
__device__ __forceinline__ uint32_t smem_u32(const void* p) {
    uint32_t a;
    asm("{ .reg .u64 t; cvta.to.shared.u64 t, %1; cvt.u32.u64 %0, t; }" : "=r"(a) : "l"(p));
    return a;
}
__device__ __forceinline__ void ldsm4(uint32_t& r0, uint32_t& r1, uint32_t& r2, uint32_t& r3,
                                      uint32_t addr) {
    asm volatile("ldmatrix.sync.aligned.m8n8.x4.shared.b16 {%0,%1,%2,%3}, [%4];"
                 : "=r"(r0), "=r"(r1), "=r"(r2), "=r"(r3) : "r"(addr));
}
__device__ __forceinline__ void mma_bf16(float* d, const uint32_t* a, uint32_t b0, uint32_t b1) {
    asm volatile("mma.sync.aligned.m16n8k16.row.col.f32.bf16.bf16.f32 "
                 "{%0,%1,%2,%3}, {%4,%5,%6,%7}, {%8,%9}, {%0,%1,%2,%3};"
                 : "+f"(d[0]), "+f"(d[1]), "+f"(d[2]), "+f"(d[3])
                 : "r"(a[0]), "r"(a[1]), "r"(a[2]), "r"(a[3]), "r"(b0), "r"(b1));
}
__device__ __forceinline__ void red_add_v4(float* gptr, float4 v) {
    asm volatile("red.global.add.v4.f32 [%0], {%1, %2, %3, %4};"
                 :: "l"(gptr), "f"(v.x), "f"(v.y), "f"(v.z), "f"(v.w) : "memory");
}

// ---------------- generic helpers ----------------
__device__ __forceinline__ float blk_reduce_256(float v) {
    __shared__ float sh[8];
    int lane = threadIdx.x & 31, w = threadIdx.x >> 5;
#pragma unroll
    for (int o = 16; o; o >>= 1) v += __shfl_down_sync(0xffffffffu, v, o);
    if (lane == 0) sh[w] = v;
    __syncthreads();
    if (w == 0) {
        v = (lane < 8) ? sh[lane] : 0.f;
#pragma unroll
        for (int o = 4; o; o >>= 1) v += __shfl_down_sync(0xffffffffu, v, o);
    }
    return v;
}

// ------- fused codebook convert + per-row squared norms + max (both) -------
// grid = (KS + KM) / 2 = 2560 blocks; [0,512) syn, [512,2560) sem.
__global__ void cvt_cb_norm_all_kernel(
    const float* __restrict__ cbA, __nv_bfloat16* __restrict__ outA,
    float* __restrict__ normsA, int* __restrict__ mxA,
    const float* __restrict__ cbB, __nv_bfloat16* __restrict__ outB,
    float* __restrict__ normsB, int* __restrict__ mxB)
{
    __shared__ float sh[8];
    int b = blockIdx.x;
    const float* cb;
    __nv_bfloat16* out;
    float* norms;
    int* mx;
    if (b < 512) { cb = cbA; out = outA; norms = normsA; mx = mxA; }
    else         { cb = cbB; out = outB; norms = normsB; mx = mxB; b -= 512; }
    int t = threadIdx.x, lane = t & 31, w = t >> 5;
    size_t e = ((size_t)b * 256 + t) * 4;
    float4 v = *(const float4*)(cb + e);
    __nv_bfloat162 a = __floats2bfloat162_rn(v.x, v.y);
    __nv_bfloat162 c = __floats2bfloat162_rn(v.z, v.w);
    ((__nv_bfloat162*)(out + e))[0] = a;
    ((__nv_bfloat162*)(out + e))[1] = c;
    float s = v.x * v.x + v.y * v.y + v.z * v.z + v.w * v.w;
#pragma unroll
    for (int o = 16; o; o >>= 1) s += __shfl_xor_sync(0xffffffffu, s, o);
    if (lane == 0) sh[w] = s;
    __syncthreads();
    if (t == 0) {
        float n0 = sh[0] + sh[1] + sh[2] + sh[3];
        norms[b * 2] = n0;
        atomicMax(mx, __float_as_int(n0));
    } else if (t == 128) {
        float n1 = sh[4] + sh[5] + sh[6] + sh[7];
        norms[b * 2 + 1] = n1;
        atomicMax(mx, __float_as_int(n1));
    }
}

// ---------------- HMMA bf16 distance pass (fused z fp32->bf16 load) --------
// Per unit (CTA, 256 thr = 8 warps in 2m x 4n): 64 rows x 1024 codes, D=512.
// Z loaded from fp32 inputs, converted inline into SMEM (row stride 1040B).
// Codebook streamed in 128 x 64 chunks (144B rows), 2 stage buffers,
// one __syncthreads per chunk. L1/crossbar-bound; structure frozen.
#define SM2_Z      0
#define SM2_C      66560
#define SM2_STAGE  18432
#define SM2_TOTAL  (SM2_C + 2 * SM2_STAGE)    // 103424
#define SM2_SV     SM2_Z
#define SM2_SK     (SM2_Z + 8192)

__global__ __launch_bounds__(256, 2) void dist_hmma_kernel(
    const float* __restrict__ zreA, const float* __restrict__ zimA,
    const __nv_bfloat16* __restrict__ cbfA, const float* __restrict__ cnA,
    const float* __restrict__ zreB, const float* __restrict__ zimB,
    const __nv_bfloat16* __restrict__ cbfB, const float* __restrict__ cnB,
    float* __restrict__ cvout, int* __restrict__ ckout)
{
    extern __shared__ __align__(16) char smem[];
    char* sZ = smem + SM2_Z;
    const uint32_t sbase = smem_u32(smem);

    const int tid = threadIdx.x, wid = tid >> 5, lane = tid & 31;
    const int u = blockIdx.x;

    const float *zre, *zim;
    const __nv_bfloat16* csrc;
    const float* cn;
    int rowBase, kBase;
    if (u < 512) {
        zre = zreA; zim = zimA; csrc = cbfA; cn = cnA; rowBase = u * 64; kBase = 0;
    } else {
        int v = u - 512;
        zre = zreB; zim = zimB; csrc = cbfB; cn = cnB;
        rowBase = (v >> 2) * 64; kBase = (v & 3) * 1024;
    }

    // load Z tile: 64 rows x 512 fp32 -> bf16 in SMEM
#pragma unroll
    for (int i = 0; i < 16; i++) {
        int c = tid + 256 * i;       // 16B-bf16 chunk id, 0..4095
        int r = c >> 6, c8 = c & 63;
        int dg = c8 * 8;             // 8 bf16 elements starting at d=dg
        const float* zs = (dg < GLD) ? zre + (size_t)(rowBase + r) * GLD + dg
                                     : zim + (size_t)(rowBase + r) * GLD + (dg - GLD);
        float4 v0 = *(const float4*)zs;
        float4 v1 = *(const float4*)(zs + 4);
        uint4 o;
        o.x = __nv_bfloat162_raw(__floats2bfloat162_rn(v0.x, v0.y)).x |
              ((uint32_t)__nv_bfloat162_raw(__floats2bfloat162_rn(v0.x, v0.y)).y << 16);
        // build packed pairs properly via raw conversion
        __nv_bfloat162 p0 = __floats2bfloat162_rn(v0.x, v0.y);
        __nv_bfloat162 p1 = __floats2bfloat162_rn(v0.z, v0.w);
        __nv_bfloat162 p2 = __floats2bfloat162_rn(v1.x, v1.y);
        __nv_bfloat162 p3 = __floats2bfloat162_rn(v1.z, v1.w);
        o.x = *(uint32_t*)&p0; o.y = *(uint32_t*)&p1;
        o.z = *(uint32_t*)&p2; o.w = *(uint32_t*)&p3;
        *(uint4*)(sZ + r * 1040 + c8 * 16) = o;
    }

    const int wm = wid >> 2, wn = wid & 3;
    const uint32_t zaddr0 = sbase + SM2_Z +
        (uint32_t)((wm * 32 + (lane & 15)) * 1040 + (lane >> 4) * 16);
    const uint32_t coff = (uint32_t)((wn * 32 + ((lane >> 4) << 3) + (lane & 7)) * 144 +
                                     ((lane >> 3) & 1) * 16);

    float tv[4][2]; int tk[4][2];
#pragma unroll
    for (int i = 0; i < 4; i++)
#pragma unroll
        for (int s = 0; s < 2; s++) { tv[i][s] = FLT_MAX; tk[i][s] = 0; }

    float acc[2][4][4];
#pragma unroll
    for (int mt = 0; mt < 2; mt++)
#pragma unroll
        for (int nt = 0; nt < 4; nt++)
#pragma unroll
            for (int q = 0; q < 4; q++) acc[mt][nt][q] = 0.f;

#define LDGC(pf, cc) do { \
        int _t = (cc) >> 3, _dc = (cc) & 7; \
        _Pragma("unroll") \
        for (int _j = 0; _j < 4; _j++) { \
            int _id = tid + 256 * _j; int _r = _id >> 3, _c8 = _id & 7; \
            (pf)[_j] = *(const uint4*)(csrc + (((size_t)(kBase + _t * 128 + _r)) << 9) \
                                       + _dc * 64 + _c8 * 8); \
        } \
    } while (0)
#define STSC(pf, cc) do { \
        char* _sp = smem + SM2_C + ((cc) & 1) * SM2_STAGE; \
        _Pragma("unroll") \
        for (int _j = 0; _j < 4; _j++) { \
            int _id = tid + 256 * _j; int _r = _id >> 3, _c8 = _id & 7; \
            *(uint4*)(_sp + _r * 144 + _c8 * 16) = (pf)[_j]; \
        } \
    } while (0)

    uint4 pf[4];
    LDGC(pf, 0);
    STSC(pf, 0);
    LDGC(pf, 1);
    __syncthreads();

    for (int c = 0; c < 64; c++) {
        if (c + 1 < 64) {
            STSC(pf, c + 1);
            if (c + 2 < 64) LDGC(pf, c + 2);
        }

        const int dc = c & 7;
        const uint32_t caddr0 = sbase + (uint32_t)(SM2_C + (c & 1) * SM2_STAGE) + coff;
#pragma unroll
        for (int ks = 0; ks < 4; ks++) {
            uint32_t b[8];
            ldsm4(b[0], b[1], b[2], b[3], caddr0 + ks * 32);
            ldsm4(b[4], b[5], b[6], b[7], caddr0 + 16 * 144 + ks * 32);
            uint32_t a[2][4];
#pragma unroll
            for (int mt = 0; mt < 2; mt++)
                ldsm4(a[mt][0], a[mt][1], a[mt][2], a[mt][3],
                      zaddr0 + (uint32_t)(mt * 16 * 1040 + (dc * 64 + ks * 16) * 2));
#pragma unroll
            for (int mt = 0; mt < 2; mt++)
#pragma unroll
                for (int nt = 0; nt < 4; nt++)
                    mma_bf16(acc[mt][nt], a[mt], b[(nt >> 1) * 4 + (nt & 1) * 2],
                             b[(nt >> 1) * 4 + (nt & 1) * 2 + 1]);
        }

        if (dc == 7) {
            const int kTile = kBase + (c >> 3) * 128;
            float cnv[8];
#pragma unroll
            for (int nt = 0; nt < 4; nt++)
#pragma unroll
                for (int cc2 = 0; cc2 < 2; cc2++)
                    cnv[nt * 2 + cc2] = __ldg(&cn[kTile + wn * 32 + nt * 8 + (lane & 3) * 2 + cc2]);
#pragma unroll
            for (int mt = 0; mt < 2; mt++)
#pragma unroll
                for (int half = 0; half < 2; half++) {
                    int i = mt * 2 + half;
#pragma unroll
                    for (int nt = 0; nt < 4; nt++)
#pragma unroll
                        for (int cc2 = 0; cc2 < 2; cc2++) {
                            int col = wn * 32 + nt * 8 + (lane & 3) * 2 + cc2;
                            float s = acc[mt][nt][half * 2 + cc2];
                            float v = fmaf(-2.f, s, cnv[nt * 2 + cc2]);
                            int k = kTile + col;
                            if (v < tv[i][0]) {
                                tv[i][1] = tv[i][0]; tk[i][1] = tk[i][0];
                                tv[i][0] = v; tk[i][0] = k;
                            } else if (v < tv[i][1]) {
                                tv[i][1] = v; tk[i][1] = k;
                            }
                        }
                }
#pragma unroll
            for (int mt = 0; mt < 2; mt++)
#pragma unroll
                for (int nt = 0; nt < 4; nt++)
#pragma unroll
                    for (int q = 0; q < 4; q++) acc[mt][nt][q] = 0.f;
        }
        __syncthreads();
    }

    float* sv = (float*)(smem + SM2_SV);
    int*   sk = (int*)(smem + SM2_SK);
#pragma unroll
    for (int i = 0; i < 4; i++) {
        int r = wm * 32 + (i >> 1) * 16 + (i & 1) * 8 + (lane >> 2);
        int slot0 = wn * 8 + (lane & 3) * 2;
#pragma unroll
        for (int s = 0; s < 2; s++) {
            sv[r * 32 + slot0 + s] = tv[i][s];
            sk[r * 32 + slot0 + s] = tk[i][s];
        }
    }
    __syncthreads();
#pragma unroll
    for (int j = 0; j < 8; j++) {
        int idx = tid + 256 * j;
        cvout[(size_t)u * 2048 + idx] = sv[idx];
        ckout[(size_t)u * 2048 + idx] = sk[idx];
    }
#undef LDGC
#undef STSC
}

// ------- fused: exact refinement + scatter + zq write + loss (warp/row) ----
__global__ __launch_bounds__(256) void refine_fuse_kernel(
    const float* __restrict__ zreA, const float* __restrict__ zimA,
    const float* __restrict__ cbA, const float* __restrict__ cnA,
    const float* __restrict__ zreB, const float* __restrict__ zimB,
    const float* __restrict__ cbB, const float* __restrict__ cnB,
    const float* __restrict__ cv, const int* __restrict__ ck,
    const int* __restrict__ maxcn,
    const int* __restrict__ prevA, const int* __restrict__ prevB,
    int* __restrict__ idxA, int* __restrict__ idxB,
    float* __restrict__ cntA, float* __restrict__ cntB,
    float* __restrict__ esA, float* __restrict__ esB,
    int* __restrict__ pairA, int* __restrict__ pairB,
    float* __restrict__ zqA, float* __restrict__ zqB,
    float* __restrict__ idxfA, float* __restrict__ idxfB,
    float* __restrict__ lossPart)
{
    int wid = threadIdx.x >> 5, lane = threadIdx.x & 31;
    int gw = blockIdx.x * 8 + wid;
    int n = gw >> 1, cbk = gw & 1;
    const float *zre, *zim, *cb, *cn;
    const int* prev;
    int* idxo;
    float *cnts, *esum, *zq, *idxf;
    int* pair;
    int cnt, K;
    size_t base;
    if (cbk == 0) {
        zre = zreA; zim = zimA; cb = cbA; cn = cnA; prev = prevA; idxo = idxA;
        cnts = cntA; esum = esA; pair = pairA; zq = zqA; idxf = idxfA;
        cnt = 32; K = KS;
        base = (size_t)(n >> 6) * 2048 + (size_t)(n & 63) * 32;
    } else {
        zre = zreB; zim = zimB; cb = cbB; cn = cnB; prev = prevB; idxo = idxB;
        cnts = cntB; esum = esB; pair = pairB; zq = zqB; idxf = idxfB;
        cnt = 128; K = KM;
        base = (size_t)(512 + (n >> 6) * 4) * 2048 + (size_t)(n & 63) * 32;
    }

    float candv[4]; int candk[4];
    const int nj = cnt >> 5;
#pragma unroll
    for (int j = 0; j < 4; j++) {
        if (j < nj) {
            size_t a = base + (size_t)j * 2048 + lane;
            candv[j] = cv[a];
            candk[j] = ck[a];
        } else { candv[j] = FLT_MAX; candk[j] = 0x7fffffff; }
    }

    float zr[16];
    float zn2 = 0.f;
#pragma unroll
    for (int j = 0; j < 16; j++) {
        int d = lane + 32 * j;
        float z = (d < GLD) ? zre[(size_t)n * GLD + d] : zim[(size_t)n * GLD + d - GLD];
        zr[j] = z;
        zn2 = fmaf(z, z, zn2);
    }
#pragma unroll
    for (int o = 16; o; o >>= 1) zn2 += __shfl_xor_sync(0xffffffffu, zn2, o);

    float vb = fminf(fminf(candv[0], candv[1]), fminf(candv[2], candv[3]));
#pragma unroll
    for (int o = 16; o; o >>= 1) vb = fminf(vb, __shfl_xor_sync(0xffffffffu, vb, o));

    float maxc2 = __int_as_float(maxcn[cbk]);
    float vlim = vb + 0.03125f * sqrtf(zn2 * maxc2) + 0.125f;

    float bd = FLT_MAX; int bk = 0x7fffffff;
    for (int i = 0; i < cnt; i++) {
        float v = __shfl_sync(0xffffffffu, candv[i >> 5], i & 31);
        if (v <= vlim) {
            int k = __shfl_sync(0xffffffffu, candk[i >> 5], i & 31);
            const float* crow = cb + (size_t)k * GD;
            float s = 0.f;
#pragma unroll
            for (int j = 0; j < 16; j++) s = fmaf(zr[j], crow[lane + 32 * j], s);
#pragma unroll
            for (int o = 16; o; o >>= 1) s += __shfl_xor_sync(0xffffffffu, s, o);
            float d = fmaf(-2.f, s, cn[k]);
            if (d < bd || (d == bd && k < bk)) { bd = d; bk = k; }
        }
    }

    // phase 2: outputs for winner bk (winner row + z lines are cache-hot)
    if (lane == 0) {
        idxo[n] = bk;
        idxf[n] = (float)bk;
        atomicAdd(&cnts[bk], 1.f);
        atomicAdd(&pair[(size_t)prev[n] * K + bk], 1);
    }
    const float* crow = cb + (size_t)bk * GD;
    float s = 0.f;
#pragma unroll
    for (int j = 0; j < 4; j++) {
        int d = lane * 4 + 128 * j;
        float4 q = *(const float4*)(crow + d);
        const float* zs = (d < GLD) ? zre + (size_t)n * GLD + d
                                    : zim + (size_t)n * GLD + (d - GLD);
        float4 z = *(const float4*)zs;
        *(float4*)(zq + (size_t)n * GD + d) = q;
        float dx = q.x - z.x, dy = q.y - z.y, dz = q.z - z.z, dw = q.w - z.w;
        s += dx * dx + dy * dy + dz * dz + dw * dw;
        red_add_v4(esum + (size_t)bk * GD + d, z);
    }
#pragma unroll
    for (int o = 16; o; o >>= 1) s += __shfl_down_sync(0xffffffffu, s, o);
    if (lane == 0) atomicAdd(&lossPart[n & 511], s);
}

// ---------------- cluster_size EMA + n reduction (both codebooks) ----------
__global__ void clnew_all_kernel(const float* __restrict__ clA, const float* __restrict__ cntA,
                                 float* __restrict__ clnewA,
                                 const float* __restrict__ clB, const float* __restrict__ cntB,
                                 float* __restrict__ clnewB,
                                 float* __restrict__ nsum)
{
    int b = blockIdx.x;
    const float *cl, *cnts;
    float* clnew;
    float* ns;
    int k;
    if (b < 4) { cl = clA; cnts = cntA; clnew = clnewA; ns = nsum;     k = b * 256 + threadIdx.x; }
    else       { cl = clB; cnts = cntB; clnew = clnewB; ns = nsum + 1; k = (b - 4) * 256 + threadIdx.x; }
    float v = cl[k] * 0.99f + 0.01f * cnts[k];
    clnew[k] = v;
    v = blk_reduce_256(v);
    if (threadIdx.x == 0) atomicAdd(ns, v);
}

// ---------------- codebook EMA update (both, float4 loads, scalar stores) --
__global__ void cbnew_all_kernel(const float* __restrict__ avgA, const float* __restrict__ esA,
                                 const float* __restrict__ clA, float* __restrict__ outA,
                                 const float* __restrict__ avgB, const float* __restrict__ esB,
                                 const float* __restrict__ clB, float* __restrict__ outB,
                                 const float* __restrict__ nsum)
{
    size_t e4 = ((size_t)blockIdx.x * 256 + threadIdx.x) * 4;
    const float *avg, *es, *cl;
    float* out;
    float n;
    size_t e;
    int K;
    if (e4 < (size_t)KS * GD) {
        avg = avgA; es = esA; cl = clA; out = outA; n = nsum[0]; e = e4; K = KS;
    } else {
        avg = avgB; es = esB; cl = clB; out = outB; n = nsum[1]; e = e4 - (size_t)KS * GD; K = KM;
    }
    int k = (int)(e >> 9);
    float cs = (cl[k] + 1e-6f) / (n + (float)K * 1e-6f) * n;
    float inv = 1.f / cs;
    float4 a = *(const float4*)(avg + e);
    float4 s = *(const float4*)(es + e);
    out[e + 0] = fmaf(a.x, 0.99f, 0.01f * s.x) * inv;
    out[e + 1] = fmaf(a.y, 0.99f, 0.01f * s.y) * inv;
    out[e + 2] = fmaf(a.z, 0.99f, 0.01f * s.z) * inv;
    out[e + 3] = fmaf(a.w, 0.99f, 0.01f * s.w) * inv;
}

__global__ void finalize_loss_kernel(const float* __restrict__ lacc, float* __restrict__ out) {
    __shared__ float sh[8];
    int t = threadIdx.x, lane = t & 31, w = t >> 5;
    float s = lacc[t] + lacc[t + 256];
#pragma unroll
    for (int o = 16; o; o >>= 1) s += __shfl_down_sync(0xffffffffu, s, o);
    if (lane == 0) sh[w] = s;
    __syncthreads();
    if (t == 0) {
        float v = 0.f;
#pragma unroll
        for (int j = 0; j < 8; j++) v += sh[j];
        out[0] = 1.25f * v / 16777216.f;
    }
}

// ---------------- sparse adjacency update (both codebooks) ----------------
__global__ void adj_sparse_all_kernel(
    const int* __restrict__ prevA, const int* __restrict__ idxA, int* __restrict__ pairA,
    const float* __restrict__ adjA, float* __restrict__ outA,
    const int* __restrict__ prevB, const int* __restrict__ idxB, int* __restrict__ pairB,
    const float* __restrict__ adjB, float* __restrict__ outB)
{
    int b = blockIdx.x;
    const int *prev, *idxv;
    int* pair;
    const float* adj;
    float* out;
    int K, n;
    if (b < 128) { prev = prevA; idxv = idxA; pair = pairA; adj = adjA; out = outA; K = KS; n = b * 256 + threadIdx.x; }
    else         { prev = prevB; idxv = idxB; pair = pairB; adj = adjB; out = outB; K = KM; n = (b - 128) * 256 + threadIdx.x; }
    size_t p = (size_t)prev[n] * K + idxv[n];
    int c = atomicExch(&pair[p], 0);
    if (c > 0) {
        float pw = __powf(0.99f, (float)c);
        out[p] = fmaf(adj[p], pw, (1.f - pw) * 100.f);
    }
}

// ---------------- launch ----------------
extern "C" void kernel_launch(void* const* d_in, const int* in_sizes, int n_in,
                              void* d_out, int out_size)
{
    const float* zre_f = (const float*)d_in[0];
    const float* zim_f = (const float*)d_in[1];
    const float* zre_s = (const float*)d_in[2];
    const float* zim_s = (const float*)d_in[3];
    const int*   prev_syn = (const int*)d_in[4];
    const int*   prev_sem = (const int*)d_in[5];
    const float* cb_syn = (const float*)d_in[6];
    const float* cb_sem = (const float*)d_in[7];
    const float* cl_syn = (const float*)d_in[8];
    const float* avg_syn = (const float*)d_in[9];
    const float* cl_sem = (const float*)d_in[10];
    const float* avg_sem = (const float*)d_in[11];
    const float* adj_syn = (const float*)d_in[12];
    const float* adj_sem = (const float*)d_in[13];

    float* out = (float*)d_out;
    const size_t OFF_ZQ_SYN = 0;
    const size_t OFF_ZQ_SEM = OFF_ZQ_SYN + (size_t)GN * GD;
    const size_t OFF_LOSS   = OFF_ZQ_SEM + (size_t)GN * GD;
    const size_t OFF_IDX_SYN = OFF_LOSS + 1;
    const size_t OFF_IDX_SEM = OFF_IDX_SYN + GN;
    const size_t OFF_CB_SYN  = OFF_IDX_SEM + GN;
    const size_t OFF_CB_SEM  = OFF_CB_SYN + (size_t)KS * GD;
    const size_t OFF_ADJ_SYN = OFF_CB_SEM + (size_t)KM * GD;
    const size_t OFF_ADJ_SEM = OFF_ADJ_SYN + (size_t)KS * KS;

    void *p_esum_syn, *p_esum_sem, *p_cnt_syn, *p_cnt_sem, *p_pair_syn, *p_pair_sem;
    void *p_idx_syn, *p_idx_sem, *p_cn_syn, *p_cn_sem, *p_cl_syn, *p_cl_sem, *p_nsum, *p_loss;
    void *p_maxcn, *p_cbf_syn, *p_cbf_sem, *p_cv, *p_ck;
    cudaGetSymbolAddress(&p_esum_syn, g_esum_syn);
    cudaGetSymbolAddress(&p_esum_sem, g_esum_sem);
    cudaGetSymbolAddress(&p_cnt_syn, g_counts_syn);
    cudaGetSymbolAddress(&p_cnt_sem, g_counts_sem);
    cudaGetSymbolAddress(&p_pair_syn, g_pair_syn);
    cudaGetSymbolAddress(&p_pair_sem, g_pair_sem);
    cudaGetSymbolAddress(&p_idx_syn, g_idx_syn);
    cudaGetSymbolAddress(&p_idx_sem, g_idx_sem);
    cudaGetSymbolAddress(&p_cn_syn, g_cnorm_syn);
    cudaGetSymbolAddress(&p_cn_sem, g_cnorm_sem);
    cudaGetSymbolAddress(&p_cl_syn, g_clnew_syn);
    cudaGetSymbolAddress(&p_cl_sem, g_clnew_sem);
    cudaGetSymbolAddress(&p_nsum, g_nsum);
    cudaGetSymbolAddress(&p_loss, g_losspart);
    cudaGetSymbolAddress(&p_maxcn, g_maxcn);
    cudaGetSymbolAddress(&p_cbf_syn, g_cbf_syn);
    cudaGetSymbolAddress(&p_cbf_sem, g_cbf_sem);
    cudaGetSymbolAddress(&p_cv, g_cv);
    cudaGetSymbolAddress(&p_ck, g_ck);

    cudaFuncSetAttribute(dist_hmma_kernel,
                         cudaFuncAttributeMaxDynamicSharedMemorySize, SM2_TOTAL);

    // 1) zero scratch (pair arrays self-draining)
    cudaMemsetAsync(p_esum_syn, 0, (size_t)KS * GD * sizeof(float));
    cudaMemsetAsync(p_esum_sem, 0, (size_t)KM * GD * sizeof(float));
    cudaMemsetAsync(p_cnt_syn, 0, KS * sizeof(float));
    cudaMemsetAsync(p_cnt_sem, 0, KM * sizeof(float));
    cudaMemsetAsync(p_nsum, 0, 2 * sizeof(float));
    cudaMemsetAsync(p_loss, 0, 512 * sizeof(float));
    cudaMemsetAsync(p_maxcn, 0, 2 * sizeof(int));

    // 2) pre-fill adjacency outputs with pass-through values
    cudaMemcpyAsync(out + OFF_ADJ_SYN, adj_syn, (size_t)KS * KS * sizeof(float),
                    cudaMemcpyDeviceToDevice);
    cudaMemcpyAsync(out + OFF_ADJ_SEM, adj_sem, (size_t)KM * KM * sizeof(float),
                    cudaMemcpyDeviceToDevice);

    // 3) codebook conversion + norms (both in one launch)
    cvt_cb_norm_all_kernel<<<(KS + KM) / 2, 256>>>(
        cb_syn, (__nv_bfloat16*)p_cbf_syn, (float*)p_cn_syn, (int*)p_maxcn,
        cb_sem, (__nv_bfloat16*)p_cbf_sem, (float*)p_cn_sem, ((int*)p_maxcn) + 1);

    // 4) HMMA approximate distance pass (z converted inline)
    dist_hmma_kernel<<<NUNITS2, 256, SM2_TOTAL>>>(
        zre_f, zim_f, (const __nv_bfloat16*)p_cbf_syn, (const float*)p_cn_syn,
        zre_s, zim_s, (const __nv_bfloat16*)p_cbf_sem, (const float*)p_cn_sem,
        (float*)p_cv, (int*)p_ck);

    // 5) fused refine + scatter + zq + loss
    refine_fuse_kernel<<<(2 * GN) / 8, 256>>>(
        zre_f, zim_f, cb_syn, (const float*)p_cn_syn,
        zre_s, zim_s, cb_sem, (const float*)p_cn_sem,
        (const float*)p_cv, (const int*)p_ck, (const int*)p_maxcn,
        prev_syn, prev_sem,
        (int*)p_idx_syn, (int*)p_idx_sem,
        (float*)p_cnt_syn, (float*)p_cnt_sem,
        (float*)p_esum_syn, (float*)p_esum_sem,
        (int*)p_pair_syn, (int*)p_pair_sem,
        out + OFF_ZQ_SYN, out + OFF_ZQ_SEM,
        out + OFF_IDX_SYN, out + OFF_IDX_SEM,
        (float*)p_loss);

    // 6) cluster size EMA + n (both)
    clnew_all_kernel<<<(KS + KM) / 256, 256>>>(
        cl_syn, (const float*)p_cnt_syn, (float*)p_cl_syn,
        cl_sem, (const float*)p_cnt_sem, (float*)p_cl_sem,
        (float*)p_nsum);

    // 7) codebook EMA update (both)
    cbnew_all_kernel<<<((KS + KM) * GD) / 1024, 256>>>(
        avg_syn, (const float*)p_esum_syn, (const float*)p_cl_syn, out + OFF_CB_SYN,
        avg_sem, (const float*)p_esum_sem, (const float*)p_cl_sem, out + OFF_CB_SEM,
        (const float*)p_nsum);

    // 8) loss finalize
    finalize_loss_kernel<<<1, 256>>>((const float*)p_loss, out + OFF_LOSS);

    // 9) sparse adjacency updates (both; drains pair counts)
    adj_sparse_all_kernel<<<(2 * GN) / 256, 256>>>(
        prev_syn, (const int*)p_idx_syn, (int*)p_pair_syn, adj_syn, out + OFF_ADJ_SYN,
        prev_sem, (const int*)p_idx_sem, (int*)p_pair_sem, adj_sem, out + OFF_ADJ_SEM);
    (void)in_sizes; (void)n_in; (void)out_size;
}